// round 13
// baseline (speedup 1.0000x reference)
#include <cuda_runtime.h>
#include <cuda_bf16.h>
#include <cstdint>

// Problem constants
#define NN   4096
#define HH   8
#define CC   512
#define DD   64
#define EPS_GN 1e-5f

// ---------------- scratch (device globals; no allocation) ----------------
__device__ float g_xt[(size_t)NN * NN];          // tf32-rounded x
__device__ float g_wt[(size_t)4 * CC * NN];      // tf32-rounded W^T [z][c][k]
__device__ __nv_bfloat16 g_qh[(size_t)NN * CC];  // Q pre-scaled by 1/8
__device__ __nv_bfloat16 g_ql[(size_t)NN * CC];
__device__ __nv_bfloat16 g_kh[(size_t)NN * CC];
__device__ __nv_bfloat16 g_kl[(size_t)NN * CC];
__device__ __nv_bfloat16 g_vh[(size_t)NN * CC];
__device__ __nv_bfloat16 g_vl[(size_t)NN * CC];
__device__ float g_skip[NN * CC];
__device__ float g_pre[NN * CC];
__device__ double g_psum[32][CC];
__device__ double g_psq[32][CC];
__device__ float g_mean[CC];
__device__ float g_rstd[CC];

// ---------------- PTX helpers (baseline ISA only) ----------------
__device__ __forceinline__ uint32_t smem_u32(const void* p) {
    uint32_t a;
    asm("{ .reg .u64 t; cvta.to.shared.u64 t, %1; cvt.u32.u64 %0, t; }"
        : "=r"(a) : "l"(p));
    return a;
}
__device__ __forceinline__ void cp_async16(uint32_t dst, const void* src) {
    asm volatile("cp.async.cg.shared.global [%0], [%1], 16;"
                 :: "r"(dst), "l"(src) : "memory");
}
__device__ __forceinline__ void cp_commit() {
    asm volatile("cp.async.commit_group;" ::: "memory");
}
template <int N>
__device__ __forceinline__ void cp_wait() {
    asm volatile("cp.async.wait_group %0;" :: "n"(N) : "memory");
}
__device__ __forceinline__ void ldm_x4(uint32_t* r, uint32_t addr) {
    asm volatile("ldmatrix.sync.aligned.m8n8.x4.shared.b16 {%0,%1,%2,%3}, [%4];"
                 : "=r"(r[0]), "=r"(r[1]), "=r"(r[2]), "=r"(r[3]) : "r"(addr));
}
__device__ __forceinline__ void ldm_x4_t(uint32_t* r, uint32_t addr) {
    asm volatile("ldmatrix.sync.aligned.m8n8.x4.trans.shared.b16 {%0,%1,%2,%3}, [%4];"
                 : "=r"(r[0]), "=r"(r[1]), "=r"(r[2]), "=r"(r[3]) : "r"(addr));
}
__device__ __forceinline__ void lds32(uint32_t& v, uint32_t addr) {
    asm volatile("ld.shared.b32 %0, [%1];" : "=r"(v) : "r"(addr));
}
__device__ __forceinline__ void mma_bf16(float* d, const uint32_t* a,
                                         uint32_t b0, uint32_t b1) {
    asm volatile(
        "mma.sync.aligned.m16n8k16.row.col.f32.bf16.bf16.f32 "
        "{%0,%1,%2,%3}, {%4,%5,%6,%7}, {%8,%9}, {%0,%1,%2,%3};"
        : "+f"(d[0]), "+f"(d[1]), "+f"(d[2]), "+f"(d[3])
        : "r"(a[0]), "r"(a[1]), "r"(a[2]), "r"(a[3]), "r"(b0), "r"(b1));
}
__device__ __forceinline__ void mma_tf32(float* d, const uint32_t* a,
                                         uint32_t b0, uint32_t b1) {
    asm volatile(
        "mma.sync.aligned.m16n8k8.row.col.f32.tf32.tf32.f32 "
        "{%0,%1,%2,%3}, {%4,%5,%6,%7}, {%8,%9}, {%0,%1,%2,%3};"
        : "+f"(d[0]), "+f"(d[1]), "+f"(d[2]), "+f"(d[3])
        : "r"(a[0]), "r"(a[1]), "r"(a[2]), "r"(a[3]), "r"(b0), "r"(b1));
}
__device__ __forceinline__ uint32_t to_tf32(float f) {
    uint32_t r;
    asm("cvt.rna.tf32.f32 %0, %1;" : "=r"(r) : "f"(f));
    return r;
}
__device__ __forceinline__ void split2(float a, float b, uint32_t& hi, uint32_t& lo) {
    __nv_bfloat16 ha = __float2bfloat16_rn(a), hb = __float2bfloat16_rn(b);
    __nv_bfloat16 la = __float2bfloat16_rn(a - __bfloat162float(ha));
    __nv_bfloat16 lb = __float2bfloat16_rn(b - __bfloat162float(hb));
    __nv_bfloat162 H(ha, hb), L(la, lb);
    hi = *(uint32_t*)&H;
    lo = *(uint32_t*)&L;
}

// ---------------- conversion kernels ----------------
__global__ __launch_bounds__(256) void convert_x(const float* __restrict__ x)
{
    size_t i = ((size_t)blockIdx.x * 256 + threadIdx.x) * 4;
    float4 v = *(const float4*)(x + i);
    uint4 o;
    o.x = to_tf32(v.x);
    o.y = to_tf32(v.y);
    o.z = to_tf32(v.z);
    o.w = to_tf32(v.w);
    *(uint4*)(g_xt + i) = o;
}

// transpose + tf32-round W: Wt[z][c][k] = W[z][k][c]; zbase selects pair
__global__ __launch_bounds__(256) void convert_w(
    const float* __restrict__ W0, const float* __restrict__ W1, int zbase)
{
    const float* W = blockIdx.z ? W1 : W0;
    __shared__ float t[32][33];
    int k0 = blockIdx.x * 32, c0 = blockIdx.y * 32;
    int tx = threadIdx.x, ty = threadIdx.y;  // 32 x 8
    #pragma unroll
    for (int i = 0; i < 4; i++)
        t[ty + i * 8][tx] = W[(size_t)(k0 + ty + i * 8) * CC + c0 + tx];
    __syncthreads();
    #pragma unroll
    for (int i = 0; i < 4; i++) {
        uint32_t v = to_tf32(t[tx][ty + i * 8]);
        size_t o = ((size_t)(zbase + blockIdx.z) * CC + c0 + ty + i * 8) * NN + k0 + tx;
        *(uint32_t*)(g_wt + o) = v;
    }
}

// ---- Kernel: tf32 GEMM, CTA 128x128, 4 warps (64x64 warp tile), 3 CTAs/SM --
#define KCH 32
#define AROWB 144                 // 36 floats row stride
#define TILE_A (128 * AROWB)      // 18432
#define TILE_B2 (128 * AROWB)     // 18432
#define STG (TILE_A + TILE_B2)    // 36864
#define NCH (NN / KCH)            // 128

__global__ __launch_bounds__(128, 3) void gemm_mma(
    const float* __restrict__ bq, const float* __restrict__ bk,
    const float* __restrict__ bv, const float* __restrict__ bs)
{
    extern __shared__ char dsm[];
    const int tid = threadIdx.x;
    const int wid = tid >> 5;      // 0..3
    const int lane = tid & 31;
    const int z = blockIdx.z;
    const int bm = blockIdx.x * 128;
    const int bn = blockIdx.y * 128;

    const float* bias;
    switch (z) {
        case 0:  bias = bq; break;
        case 1:  bias = bk; break;
        case 2:  bias = bv; break;
        default: bias = bs; break;
    }

    const uint32_t sbase = smem_u32(dsm);
    const float* srcA = g_xt + (size_t)bm * NN;
    const float* srcB = g_wt + ((size_t)z * CC + bn) * NN;

    // stage layout: [A 128x144B | B 128x144B]
    auto load_stage = [&](int stage, int k0) {
        const uint32_t sb = sbase + stage * STG;
        #pragma unroll
        for (int t = 0; t < 16; t++) {
            int idx = tid + t * 128;              // 0..2047
            if (idx < 1024) {                     // A: 1024 float4
                int row = idx >> 3, c4 = idx & 7;
                cp_async16(sb + row * AROWB + c4 * 16,
                           srcA + (size_t)row * NN + k0 + c4 * 4);
            } else {                              // B: 1024 float4
                int bi = idx - 1024;
                int row = bi >> 3, c4 = bi & 7;
                cp_async16(sb + TILE_A + row * AROWB + c4 * 16,
                           srcB + (size_t)row * NN + k0 + c4 * 4);
            }
        }
        cp_commit();
    };

    float acc[4][8][4];
    #pragma unroll
    for (int i = 0; i < 4; i++)
        #pragma unroll
        for (int j = 0; j < 8; j++)
            #pragma unroll
            for (int r = 0; r < 4; r++) acc[i][j][r] = 0.f;

    const int wm = wid >> 1;       // 0..1 -> m offset wm*64
    const int wn = wid & 1;        // 0..1 -> n offset wn*64
    const int qr = lane >> 2;      // 0..7
    const int qc = lane & 3;       // 0..3

    load_stage(0, 0);

    for (int ch = 0; ch < NCH; ch++) {
        if (ch + 1 < NCH) { load_stage((ch + 1) & 1, (ch + 1) * KCH); cp_wait<1>(); }
        else              { cp_wait<0>(); }
        __syncthreads();

        const uint32_t sA = sbase + (ch & 1) * STG;
        const uint32_t sB = sA + TILE_A;

        #pragma unroll
        for (int ks8 = 0; ks8 < 4; ks8++) {
            const int kb = ks8 * 8;
            uint32_t a[4][4];
            #pragma unroll
            for (int mi = 0; mi < 4; mi++) {
                int row = wm * 64 + mi * 16 + qr;
                uint32_t off = sA + row * AROWB + (kb + qc) * 4;
                lds32(a[mi][0], off);
                lds32(a[mi][2], off + 16);
                lds32(a[mi][1], off + 8 * AROWB);
                lds32(a[mi][3], off + 8 * AROWB + 16);
            }
            #pragma unroll
            for (int ni = 0; ni < 8; ni++) {
                int nrow = wn * 64 + ni * 8 + qr;
                uint32_t boff = sB + nrow * AROWB + (kb + qc) * 4;
                uint32_t b0, b1;
                lds32(b0, boff);
                lds32(b1, boff + 16);
                #pragma unroll
                for (int mi = 0; mi < 4; mi++)
                    mma_tf32(acc[mi][ni], a[mi], b0, b1);
            }
        }
        __syncthreads();
    }

    // epilogue: z<3 -> split bf16 hi/lo (z==0 additionally scaled by 1/8);
    //           z==3 -> fp32 skip
    if (z < 3) {
        __nv_bfloat16 *Oh, *Ol;
        if (z == 0)      { Oh = g_qh; Ol = g_ql; }
        else if (z == 1) { Oh = g_kh; Ol = g_kl; }
        else             { Oh = g_vh; Ol = g_vl; }
        const float sc = (z == 0) ? 0.125f : 1.0f;
        #pragma unroll
        for (int mi = 0; mi < 4; mi++) {
            int row = bm + wm * 64 + mi * 16 + (lane >> 2);
            #pragma unroll
            for (int ni = 0; ni < 8; ni++) {
                int col = bn + wn * 64 + ni * 8 + (lane & 3) * 2;
                float2 b2 = *(const float2*)(bias + col);
                float v00 = (acc[mi][ni][0] + b2.x) * sc;
                float v01 = (acc[mi][ni][1] + b2.y) * sc;
                float v10 = (acc[mi][ni][2] + b2.x) * sc;
                float v11 = (acc[mi][ni][3] + b2.y) * sc;
                uint32_t h0, l0, h1, l1;
                split2(v00, v01, h0, l0);
                split2(v10, v11, h1, l1);
                *(uint32_t*)(Oh + (size_t)row * CC + col)       = h0;
                *(uint32_t*)(Ol + (size_t)row * CC + col)       = l0;
                *(uint32_t*)(Oh + (size_t)(row + 8) * CC + col) = h1;
                *(uint32_t*)(Ol + (size_t)(row + 8) * CC + col) = l1;
            }
        }
    } else {
        #pragma unroll
        for (int mi = 0; mi < 4; mi++) {
            int row = bm + wm * 64 + mi * 16 + (lane >> 2);
            #pragma unroll
            for (int ni = 0; ni < 8; ni++) {
                int col = bn + wn * 64 + ni * 8 + (lane & 3) * 2;
                float2 b2 = *(const float2*)(bias + col);
                float2 o0 = { acc[mi][ni][0] + b2.x, acc[mi][ni][1] + b2.y };
                float2 o1 = { acc[mi][ni][2] + b2.x, acc[mi][ni][3] + b2.y };
                *(float2*)(g_skip + (size_t)row * CC + col)       = o0;
                *(float2*)(g_skip + (size_t)(row + 8) * CC + col) = o1;
            }
        }
    }
}

// ---- Kernel 2: flash attention, 64-row CTA x 4 warps (bf16 split) ----------
#define KSTR 144                 // K/V smem row stride bytes (72 bf16)
#define KVT  (64 * KSTR)         // 9216
#define XSTR2 272                // Xa smem row stride bytes (68 floats)
#define XAT2 (64 * XSTR2)        // 17408
#define ASTG2 (4 * KVT + XAT2)   // 54272
#define NJT  (NN / 64)           // 64 j-tiles

__global__ __launch_bounds__(128, 2) void attn_mma(
    const float* __restrict__ x, const float* __restrict__ we)
{
    extern __shared__ char dsm[];
    const int tid = threadIdx.x;
    const int wid = tid >> 5;          // 0..3
    const int lane = tid & 31;
    const int h  = blockIdx.y;
    const int i0 = blockIdx.x * 64;

    const uint32_t sbase = smem_u32(dsm);

    // ---- Q fragments from gmem (pre-scaled by 1/8), plus qe = (q/8)·we ----
    uint32_t qh[4][4], ql[4][4];
    float qe0 = 0.f, qe1 = 0.f;
    {
        const int r0 = i0 + wid * 16 + (lane >> 2);
        const int cb = h * DD + (lane & 3) * 2;
        #pragma unroll
        for (int ks = 0; ks < 4; ks++) {
            #pragma unroll
            for (int p = 0; p < 4; p++) {
                int row = r0 + ((p & 1) ? 8 : 0);
                int col = cb + ks * 16 + ((p >> 1) ? 8 : 0);
                qh[ks][p] = *(const uint32_t*)(g_qh + (size_t)row * CC + col);
                ql[ks][p] = *(const uint32_t*)(g_ql + (size_t)row * CC + col);
                __nv_bfloat162 H = *(__nv_bfloat162*)&qh[ks][p];
                __nv_bfloat162 L = *(__nv_bfloat162*)&ql[ks][p];
                float v0 = __bfloat162float(H.x) + __bfloat162float(L.x);
                float v1 = __bfloat162float(H.y) + __bfloat162float(L.y);
                float w0 = __ldg(we + col);
                float w1 = __ldg(we + col + 1);
                float c = fmaf(v0, w0, v1 * w1);
                if (p & 1) qe1 += c; else qe0 += c;
            }
        }
        qe0 += __shfl_xor_sync(0xffffffffu, qe0, 1);
        qe0 += __shfl_xor_sync(0xffffffffu, qe0, 2);
        qe1 += __shfl_xor_sync(0xffffffffu, qe1, 1);
        qe1 += __shfl_xor_sync(0xffffffffu, qe1, 2);
    }

    auto load_stage = [&](int st, int j0) {
        const uint32_t sb = sbase + st * ASTG2;
        #pragma unroll
        for (int n = 0; n < 16; n++) {
            int id = tid + n * 128;              // 0..2047
            int tile = id >> 9;                  // Kh,Kl,Vh,Vl
            int rem = id & 511;
            int row = rem >> 3, c16 = rem & 7;
            const __nv_bfloat16* src =
                (tile == 0 ? g_kh : tile == 1 ? g_kl : tile == 2 ? g_vh : g_vl);
            cp_async16(sb + tile * KVT + row * KSTR + c16 * 16,
                       src + (size_t)(j0 + row) * CC + h * DD + c16 * 8);
        }
        #pragma unroll
        for (int n = 0; n < 8; n++) {
            int id = tid + n * 128;              // 0..1023
            int row = id >> 4, c16 = id & 15;
            cp_async16(sb + 4 * KVT + row * XSTR2 + c16 * 16,
                       x + (size_t)(j0 + row) * NN + i0 + c16 * 4);
        }
        cp_commit();
    };

    float o[8][4];
    #pragma unroll
    for (int nd = 0; nd < 8; nd++)
        #pragma unroll
        for (int r = 0; r < 4; r++) o[nd][r] = 0.f;
    float m0 = -1e30f, m1 = -1e30f, l0 = 0.f, l1 = 0.f, sa0 = 0.f, sa1 = 0.f;

    const int b_col = (lane & 7) + ((lane >> 4) << 3);
    const int b_k8  = ((lane >> 3) & 1) * 8;
    const int vrow  = (lane & 7) + ((lane >> 3) & 1) * 8;
    const int vcol8 = ((lane >> 4) & 1) * 8;
    const int iloc0 = wid * 16 + (lane >> 2);    // 0..63

    load_stage(0, 0);

    for (int jt = 0; jt < NJT; jt++) {
        if (jt + 1 < NJT) { load_stage((jt + 1) & 1, (jt + 1) * 64); cp_wait<1>(); }
        else              { cp_wait<0>(); }
        __syncthreads();

        const uint32_t sb = sbase + (jt & 1) * ASTG2;
        const float* xa = (const float*)(dsm + (size_t)(jt & 1) * ASTG2 + 4 * KVT);

        // ---- S = (Q/8)·K^T via split MMA ----
        float s[8][4];
        #pragma unroll
        for (int nb = 0; nb < 8; nb++)
            #pragma unroll
            for (int r = 0; r < 4; r++) s[nb][r] = 0.f;

        #pragma unroll
        for (int ks = 0; ks < 4; ks++) {
            uint32_t kh4[4][4], kl4[4][4];
            #pragma unroll
            for (int nb16 = 0; nb16 < 4; nb16++) {
                uint32_t off = (nb16 * 16 + b_col) * KSTR + (ks * 16 + b_k8) * 2;
                ldm_x4(kh4[nb16], sb + off);
                ldm_x4(kl4[nb16], sb + KVT + off);
            }
            #pragma unroll
            for (int nb = 0; nb < 8; nb++) {
                int np = nb >> 1, wh = (nb & 1) * 2;
                mma_bf16(s[nb], qh[ks], kh4[np][wh], kh4[np][wh + 1]);
                mma_bf16(s[nb], qh[ks], kl4[np][wh], kl4[np][wh + 1]);
                mma_bf16(s[nb], ql[ks], kh4[np][wh], kh4[np][wh + 1]);
            }
        }

        // ---- edge term + tile max ----
        float tm0 = -1e30f, tm1 = -1e30f;
        #pragma unroll
        for (int nb = 0; nb < 8; nb++) {
            int j = nb * 8 + 2 * (lane & 3);
            float x00 = xa[j * 68 + iloc0];
            float x01 = xa[(j + 1) * 68 + iloc0];
            float x10 = xa[j * 68 + iloc0 + 8];
            float x11 = xa[(j + 1) * 68 + iloc0 + 8];
            s[nb][0] = fmaf(x00, qe0, s[nb][0]);
            s[nb][1] = fmaf(x01, qe0, s[nb][1]);
            s[nb][2] = fmaf(x10, qe1, s[nb][2]);
            s[nb][3] = fmaf(x11, qe1, s[nb][3]);
            tm0 = fmaxf(tm0, fmaxf(s[nb][0], s[nb][1]));
            tm1 = fmaxf(tm1, fmaxf(s[nb][2], s[nb][3]));
        }
        tm0 = fmaxf(tm0, __shfl_xor_sync(0xffffffffu, tm0, 1));
        tm0 = fmaxf(tm0, __shfl_xor_sync(0xffffffffu, tm0, 2));
        tm1 = fmaxf(tm1, __shfl_xor_sync(0xffffffffu, tm1, 1));
        tm1 = fmaxf(tm1, __shfl_xor_sync(0xffffffffu, tm1, 2));

        float m0n = fmaxf(m0, tm0), m1n = fmaxf(m1, tm1);
        float sc0 = __expf(m0 - m0n), sc1 = __expf(m1 - m1n);
        l0 *= sc0; sa0 *= sc0; l1 *= sc1; sa1 *= sc1;
        #pragma unroll
        for (int nd = 0; nd < 8; nd++) {
            o[nd][0] *= sc0; o[nd][1] *= sc0;
            o[nd][2] *= sc1; o[nd][3] *= sc1;
        }
        m0 = m0n; m1 = m1n;

        // ---- p = exp(s-m); accumulate l, sacc; overwrite s with p ----
        #pragma unroll
        for (int nb = 0; nb < 8; nb++) {
            int j = nb * 8 + 2 * (lane & 3);
            float p0 = __expf(s[nb][0] - m0);
            float p1 = __expf(s[nb][1] - m0);
            float p2 = __expf(s[nb][2] - m1);
            float p3 = __expf(s[nb][3] - m1);
            l0 += p0 + p1; l1 += p2 + p3;
            float x00 = xa[j * 68 + iloc0];
            float x01 = xa[(j + 1) * 68 + iloc0];
            float x10 = xa[j * 68 + iloc0 + 8];
            float x11 = xa[(j + 1) * 68 + iloc0 + 8];
            sa0 = fmaf(p0, x00, fmaf(p1, x01, sa0));
            sa1 = fmaf(p2, x10, fmaf(p3, x11, sa1));
            s[nb][0] = p0; s[nb][1] = p1; s[nb][2] = p2; s[nb][3] = p3;
        }

        // ---- O += P·V (split) ----
        #pragma unroll
        for (int ks = 0; ks < 4; ks++) {
            uint32_t ph[4], pl[4];
            split2(s[2 * ks][0],     s[2 * ks][1],     ph[0], pl[0]);
            split2(s[2 * ks][2],     s[2 * ks][3],     ph[1], pl[1]);
            split2(s[2 * ks + 1][0], s[2 * ks + 1][1], ph[2], pl[2]);
            split2(s[2 * ks + 1][2], s[2 * ks + 1][3], ph[3], pl[3]);
            #pragma unroll
            for (int ndp = 0; ndp < 4; ndp++) {
                uint32_t vh4[4], vl4[4];
                uint32_t off = (ks * 16 + vrow) * KSTR + (ndp * 16 + vcol8) * 2;
                ldm_x4_t(vh4, sb + 2 * KVT + off);
                ldm_x4_t(vl4, sb + 3 * KVT + off);
                #pragma unroll
                for (int sub = 0; sub < 2; sub++) {
                    int nd = ndp * 2 + sub;
                    mma_bf16(o[nd], ph, vh4[sub * 2], vh4[sub * 2 + 1]);
                    mma_bf16(o[nd], ph, vl4[sub * 2], vl4[sub * 2 + 1]);
                    mma_bf16(o[nd], pl, vh4[sub * 2], vh4[sub * 2 + 1]);
                }
            }
        }
        __syncthreads();
    }

    // ---- epilogue: reduce l/sacc over quad, combine, write g_pre ----
    l0 += __shfl_xor_sync(0xffffffffu, l0, 1);
    l0 += __shfl_xor_sync(0xffffffffu, l0, 2);
    l1 += __shfl_xor_sync(0xffffffffu, l1, 1);
    l1 += __shfl_xor_sync(0xffffffffu, l1, 2);
    sa0 += __shfl_xor_sync(0xffffffffu, sa0, 1);
    sa0 += __shfl_xor_sync(0xffffffffu, sa0, 2);
    sa1 += __shfl_xor_sync(0xffffffffu, sa1, 1);
    sa1 += __shfl_xor_sync(0xffffffffu, sa1, 2);

    float inv0 = 1.f / l0, inv1 = 1.f / l1;
    float se0 = sa0 * inv0, se1 = sa1 * inv1;
    const int gr0 = i0 + wid * 16 + (lane >> 2);
    #pragma unroll
    for (int nd = 0; nd < 8; nd++) {
        int c = h * DD + nd * 8 + 2 * (lane & 3);
        float2 wv  = *(const float2*)(we + c);
        float2 sk0 = *(const float2*)(g_skip + (size_t)gr0 * CC + c);
        float2 sk1 = *(const float2*)(g_skip + (size_t)(gr0 + 8) * CC + c);
        float2 r0, r1;
        r0.x = fmaf(o[nd][0], inv0, fmaf(se0, wv.x, sk0.x));
        r0.y = fmaf(o[nd][1], inv0, fmaf(se0, wv.y, sk0.y));
        r1.x = fmaf(o[nd][2], inv1, fmaf(se1, wv.x, sk1.x));
        r1.y = fmaf(o[nd][3], inv1, fmaf(se1, wv.y, sk1.y));
        *(float2*)(g_pre + (size_t)gr0 * CC + c)       = r0;
        *(float2*)(g_pre + (size_t)(gr0 + 8) * CC + c) = r1;
    }
}

// ---------------- Kernel 3/4: GraphNorm column stats ----------------
__global__ __launch_bounds__(128) void stats_partial()
{
    int c  = blockIdx.x * 128 + threadIdx.x;
    int r0 = blockIdx.y * 128;
    double s = 0.0, s2 = 0.0;
    for (int r = r0; r < r0 + 128; r++) {
        float v = g_pre[(size_t)r * CC + c];
        s  += (double)v;
        s2 += (double)v * (double)v;
    }
    g_psum[blockIdx.y][c] = s;
    g_psq [blockIdx.y][c] = s2;
}

__global__ __launch_bounds__(128) void stats_final(const float* __restrict__ gn_ms)
{
    int c = blockIdx.x * 128 + threadIdx.x;
    double s = 0.0, s2 = 0.0;
    #pragma unroll
    for (int p = 0; p < 32; p++) { s += g_psum[p][c]; s2 += g_psq[p][c]; }
    float mean = (float)(s * (1.0 / NN));
    float ex2  = (float)(s2 * (1.0 / NN));
    float ms   = gn_ms[c];
    float var  = ex2 - 2.f * ms * mean * mean + ms * ms * mean * mean;
    g_mean[c] = mean;
    g_rstd[c] = rsqrtf(var + EPS_GN);
}

// ---------------- Kernel 5: GraphNorm apply + per-row L2 ----------------
__global__ __launch_bounds__(128) void finalize_kernel(
    const float* __restrict__ gn_w, const float* __restrict__ gn_b,
    const float* __restrict__ gn_ms, float* __restrict__ out)
{
    int r = blockIdx.x;
    int tid = threadIdx.x;
    __shared__ float red[4];

    float vals[4];
    float ss = 0.f;
    #pragma unroll
    for (int it = 0; it < 4; it++) {
        int c = tid + it * 128;
        float v = g_pre[(size_t)r * CC + c];
        v = fmaf(gn_w[c] * g_rstd[c], v - gn_ms[c] * g_mean[c], gn_b[c]);
        vals[it] = v;
        ss += v * v;
    }
    #pragma unroll
    for (int off = 16; off; off >>= 1)
        ss += __shfl_xor_sync(0xffffffffu, ss, off);
    if ((tid & 31) == 0) red[tid >> 5] = ss;
    __syncthreads();
    float tot = red[0] + red[1] + red[2] + red[3];
    float inv = rsqrtf(tot);
    #pragma unroll
    for (int it = 0; it < 4; it++)
        out[(size_t)r * CC + tid + it * 128] = vals[it] * inv;
}

// ---------------- launch ----------------
extern "C" void kernel_launch(void* const* d_in, const int* in_sizes, int n_in,
                              void* d_out, int out_size)
{
    const float* x     = (const float*)d_in[0];
    const float* Wq    = (const float*)d_in[1];
    const float* bq    = (const float*)d_in[2];
    const float* Wk    = (const float*)d_in[3];
    const float* bk    = (const float*)d_in[4];
    const float* Wv    = (const float*)d_in[5];
    const float* bv    = (const float*)d_in[6];
    const float* we    = (const float*)d_in[7];
    const float* Wskip = (const float*)d_in[8];
    const float* bskip = (const float*)d_in[9];
    const float* gn_w  = (const float*)d_in[10];
    const float* gn_b  = (const float*)d_in[11];
    const float* gn_ms = (const float*)d_in[12];
    float* out = (float*)d_out;

    const int GEMM_SMEM = 2 * STG;       // 73728 -> 3 CTAs/SM
    cudaFuncSetAttribute(gemm_mma, cudaFuncAttributeMaxDynamicSharedMemorySize,
                         GEMM_SMEM);
    const int ATTN_SMEM = 2 * ASTG2;     // 108544
    cudaFuncSetAttribute(attn_mma, cudaFuncAttributeMaxDynamicSharedMemorySize,
                         ATTN_SMEM);

    convert_x<<<(NN * (size_t)NN) / (256 * 4), 256>>>(x);
    // convert_w split so gemm_mma is launch #4 (profiled)
    convert_w<<<dim3(NN / 32, CC / 32, 2), dim3(32, 8)>>>(Wq, Wk, 0);
    convert_w<<<dim3(NN / 32, CC / 32, 2), dim3(32, 8)>>>(Wv, Wskip, 2);

    gemm_mma<<<dim3(NN / 128, CC / 128, 4), 128, GEMM_SMEM>>>(bq, bk, bv, bskip);

    attn_mma<<<dim3(NN / 64, HH), 128, ATTN_SMEM>>>(x, we);

    stats_partial<<<dim3(4, 32), 128>>>();
    stats_final<<<4, 128>>>(gn_ms);
    finalize_kernel<<<NN, 128>>>(gn_w, gn_b, gn_ms, out);
}

// round 14
// speedup vs baseline: 1.0545x; 1.0545x over previous
#include <cuda_runtime.h>
#include <cuda_bf16.h>
#include <cstdint>

// Problem constants
#define NN   4096
#define HH   8
#define CC   512
#define DD   64
#define EPS_GN 1e-5f

// ---------------- scratch (device globals; no allocation) ----------------
__device__ float g_xt[(size_t)NN * NN];          // tf32-rounded x
__device__ float g_wt[(size_t)4 * CC * NN];      // tf32-rounded W^T [z][c][k]
__device__ float g_qt[(size_t)NN * CC];          // tf32 Q (pre-scaled 1/8)
__device__ float g_kt[(size_t)NN * CC];          // tf32 K
__device__ __nv_bfloat16 g_vh[(size_t)NN * CC];
__device__ __nv_bfloat16 g_vl[(size_t)NN * CC];
__device__ float g_skip[NN * CC];
__device__ float g_pre[NN * CC];
__device__ double g_psum[32][CC];
__device__ double g_psq[32][CC];
__device__ float g_mean[CC];
__device__ float g_rstd[CC];

// ---------------- PTX helpers (baseline ISA only) ----------------
__device__ __forceinline__ uint32_t smem_u32(const void* p) {
    uint32_t a;
    asm("{ .reg .u64 t; cvta.to.shared.u64 t, %1; cvt.u32.u64 %0, t; }"
        : "=r"(a) : "l"(p));
    return a;
}
__device__ __forceinline__ void cp_async16(uint32_t dst, const void* src) {
    asm volatile("cp.async.cg.shared.global [%0], [%1], 16;"
                 :: "r"(dst), "l"(src) : "memory");
}
__device__ __forceinline__ void cp_commit() {
    asm volatile("cp.async.commit_group;" ::: "memory");
}
template <int N>
__device__ __forceinline__ void cp_wait() {
    asm volatile("cp.async.wait_group %0;" :: "n"(N) : "memory");
}
__device__ __forceinline__ void ldm_x4_t(uint32_t* r, uint32_t addr) {
    asm volatile("ldmatrix.sync.aligned.m8n8.x4.trans.shared.b16 {%0,%1,%2,%3}, [%4];"
                 : "=r"(r[0]), "=r"(r[1]), "=r"(r[2]), "=r"(r[3]) : "r"(addr));
}
__device__ __forceinline__ void lds32(uint32_t& v, uint32_t addr) {
    asm volatile("ld.shared.b32 %0, [%1];" : "=r"(v) : "r"(addr));
}
__device__ __forceinline__ void mma_bf16(float* d, const uint32_t* a,
                                         uint32_t b0, uint32_t b1) {
    asm volatile(
        "mma.sync.aligned.m16n8k16.row.col.f32.bf16.bf16.f32 "
        "{%0,%1,%2,%3}, {%4,%5,%6,%7}, {%8,%9}, {%0,%1,%2,%3};"
        : "+f"(d[0]), "+f"(d[1]), "+f"(d[2]), "+f"(d[3])
        : "r"(a[0]), "r"(a[1]), "r"(a[2]), "r"(a[3]), "r"(b0), "r"(b1));
}
__device__ __forceinline__ void mma_tf32(float* d, const uint32_t* a,
                                         uint32_t b0, uint32_t b1) {
    asm volatile(
        "mma.sync.aligned.m16n8k8.row.col.f32.tf32.tf32.f32 "
        "{%0,%1,%2,%3}, {%4,%5,%6,%7}, {%8,%9}, {%0,%1,%2,%3};"
        : "+f"(d[0]), "+f"(d[1]), "+f"(d[2]), "+f"(d[3])
        : "r"(a[0]), "r"(a[1]), "r"(a[2]), "r"(a[3]), "r"(b0), "r"(b1));
}
__device__ __forceinline__ uint32_t to_tf32(float f) {
    uint32_t r;
    asm("cvt.rna.tf32.f32 %0, %1;" : "=r"(r) : "f"(f));
    return r;
}
__device__ __forceinline__ void split2(float a, float b, uint32_t& hi, uint32_t& lo) {
    __nv_bfloat16 ha = __float2bfloat16_rn(a), hb = __float2bfloat16_rn(b);
    __nv_bfloat16 la = __float2bfloat16_rn(a - __bfloat162float(ha));
    __nv_bfloat16 lb = __float2bfloat16_rn(b - __bfloat162float(hb));
    __nv_bfloat162 H(ha, hb), L(la, lb);
    hi = *(uint32_t*)&H;
    lo = *(uint32_t*)&L;
}

// ---------------- conversion kernels ----------------
__global__ __launch_bounds__(256) void convert_x(const float* __restrict__ x)
{
    size_t i = ((size_t)blockIdx.x * 256 + threadIdx.x) * 4;
    float4 v = *(const float4*)(x + i);
    uint4 o;
    o.x = to_tf32(v.x);
    o.y = to_tf32(v.y);
    o.z = to_tf32(v.z);
    o.w = to_tf32(v.w);
    *(uint4*)(g_xt + i) = o;
}

// transpose + tf32-round W: Wt[z][c][k] = W[z][k][c]; zbase selects pair
__global__ __launch_bounds__(256) void convert_w(
    const float* __restrict__ W0, const float* __restrict__ W1, int zbase)
{
    const float* W = blockIdx.z ? W1 : W0;
    __shared__ float t[32][33];
    int k0 = blockIdx.x * 32, c0 = blockIdx.y * 32;
    int tx = threadIdx.x, ty = threadIdx.y;  // 32 x 8
    #pragma unroll
    for (int i = 0; i < 4; i++)
        t[ty + i * 8][tx] = W[(size_t)(k0 + ty + i * 8) * CC + c0 + tx];
    __syncthreads();
    #pragma unroll
    for (int i = 0; i < 4; i++) {
        uint32_t v = to_tf32(t[tx][ty + i * 8]);
        size_t o = ((size_t)(zbase + blockIdx.z) * CC + c0 + ty + i * 8) * NN + k0 + tx;
        *(uint32_t*)(g_wt + o) = v;
    }
}

// ---- Kernel: tf32 GEMM, CTA 128x128, 4 warps (64x64 warp tile), 2 CTAs/SM --
#define KCH 32
#define AROWB 144                 // 36 floats row stride
#define TILE_A (128 * AROWB)      // 18432
#define TILE_B2 (128 * AROWB)     // 18432
#define STG (TILE_A + TILE_B2)    // 36864
#define NCH (NN / KCH)            // 128

__global__ __launch_bounds__(128, 2) void gemm_mma(
    const float* __restrict__ bq, const float* __restrict__ bk,
    const float* __restrict__ bv, const float* __restrict__ bs)
{
    extern __shared__ char dsm[];
    const int tid = threadIdx.x;
    const int wid = tid >> 5;      // 0..3
    const int lane = tid & 31;
    const int z = blockIdx.z;
    const int bm = blockIdx.x * 128;
    const int bn = blockIdx.y * 128;

    const float* bias;
    switch (z) {
        case 0:  bias = bq; break;
        case 1:  bias = bk; break;
        case 2:  bias = bv; break;
        default: bias = bs; break;
    }

    const uint32_t sbase = smem_u32(dsm);
    const float* srcA = g_xt + (size_t)bm * NN;
    const float* srcB = g_wt + ((size_t)z * CC + bn) * NN;

    // stage layout: [A 128x144B | B 128x144B]
    auto load_stage = [&](int stage, int k0) {
        const uint32_t sb = sbase + stage * STG;
        #pragma unroll
        for (int t = 0; t < 16; t++) {
            int idx = tid + t * 128;              // 0..2047
            if (idx < 1024) {                     // A: 1024 float4
                int row = idx >> 3, c4 = idx & 7;
                cp_async16(sb + row * AROWB + c4 * 16,
                           srcA + (size_t)row * NN + k0 + c4 * 4);
            } else {                              // B: 1024 float4
                int bi = idx - 1024;
                int row = bi >> 3, c4 = bi & 7;
                cp_async16(sb + TILE_A + row * AROWB + c4 * 16,
                           srcB + (size_t)row * NN + k0 + c4 * 4);
            }
        }
        cp_commit();
    };

    float acc[4][8][4];
    #pragma unroll
    for (int i = 0; i < 4; i++)
        #pragma unroll
        for (int j = 0; j < 8; j++)
            #pragma unroll
            for (int r = 0; r < 4; r++) acc[i][j][r] = 0.f;

    const int wm = wid >> 1;       // 0..1 -> m offset wm*64
    const int wn = wid & 1;        // 0..1 -> n offset wn*64
    const int qr = lane >> 2;      // 0..7
    const int qc = lane & 3;       // 0..3

    load_stage(0, 0);

    for (int ch = 0; ch < NCH; ch++) {
        if (ch + 1 < NCH) { load_stage((ch + 1) & 1, (ch + 1) * KCH); cp_wait<1>(); }
        else              { cp_wait<0>(); }
        __syncthreads();

        const uint32_t sA = sbase + (ch & 1) * STG;
        const uint32_t sB = sA + TILE_A;

        #pragma unroll
        for (int ks8 = 0; ks8 < 4; ks8++) {
            const int kb = ks8 * 8;
            uint32_t a[4][4];
            #pragma unroll
            for (int mi = 0; mi < 4; mi++) {
                int row = wm * 64 + mi * 16 + qr;
                uint32_t off = sA + row * AROWB + (kb + qc) * 4;
                lds32(a[mi][0], off);
                lds32(a[mi][2], off + 16);
                lds32(a[mi][1], off + 8 * AROWB);
                lds32(a[mi][3], off + 8 * AROWB + 16);
            }
            #pragma unroll
            for (int ni = 0; ni < 8; ni++) {
                int nrow = wn * 64 + ni * 8 + qr;
                uint32_t boff = sB + nrow * AROWB + (kb + qc) * 4;
                uint32_t b0, b1;
                lds32(b0, boff);
                lds32(b1, boff + 16);
                #pragma unroll
                for (int mi = 0; mi < 4; mi++)
                    mma_tf32(acc[mi][ni], a[mi], b0, b1);
            }
        }
        __syncthreads();
    }

    // epilogue: z==0 -> tf32 fp32 Q (scaled 1/8); z==1 -> tf32 fp32 K;
    //           z==2 -> bf16 hi/lo V;       z==3 -> fp32 skip
    if (z < 2) {
        float* Ot = z ? g_kt : g_qt;
        const float sc = (z == 0) ? 0.125f : 1.0f;
        #pragma unroll
        for (int mi = 0; mi < 4; mi++) {
            int row = bm + wm * 64 + mi * 16 + (lane >> 2);
            #pragma unroll
            for (int ni = 0; ni < 8; ni++) {
                int col = bn + wn * 64 + ni * 8 + (lane & 3) * 2;
                float2 b2 = *(const float2*)(bias + col);
                uint2 o0, o1;
                o0.x = to_tf32((acc[mi][ni][0] + b2.x) * sc);
                o0.y = to_tf32((acc[mi][ni][1] + b2.y) * sc);
                o1.x = to_tf32((acc[mi][ni][2] + b2.x) * sc);
                o1.y = to_tf32((acc[mi][ni][3] + b2.y) * sc);
                *(uint2*)(Ot + (size_t)row * CC + col)       = o0;
                *(uint2*)(Ot + (size_t)(row + 8) * CC + col) = o1;
            }
        }
    } else if (z == 2) {
        #pragma unroll
        for (int mi = 0; mi < 4; mi++) {
            int row = bm + wm * 64 + mi * 16 + (lane >> 2);
            #pragma unroll
            for (int ni = 0; ni < 8; ni++) {
                int col = bn + wn * 64 + ni * 8 + (lane & 3) * 2;
                float2 b2 = *(const float2*)(bias + col);
                float v00 = acc[mi][ni][0] + b2.x;
                float v01 = acc[mi][ni][1] + b2.y;
                float v10 = acc[mi][ni][2] + b2.x;
                float v11 = acc[mi][ni][3] + b2.y;
                uint32_t h0, l0, h1, l1;
                split2(v00, v01, h0, l0);
                split2(v10, v11, h1, l1);
                *(uint32_t*)(g_vh + (size_t)row * CC + col)       = h0;
                *(uint32_t*)(g_vl + (size_t)row * CC + col)       = l0;
                *(uint32_t*)(g_vh + (size_t)(row + 8) * CC + col) = h1;
                *(uint32_t*)(g_vl + (size_t)(row + 8) * CC + col) = l1;
            }
        }
    } else {
        #pragma unroll
        for (int mi = 0; mi < 4; mi++) {
            int row = bm + wm * 64 + mi * 16 + (lane >> 2);
            #pragma unroll
            for (int ni = 0; ni < 8; ni++) {
                int col = bn + wn * 64 + ni * 8 + (lane & 3) * 2;
                float2 b2 = *(const float2*)(bias + col);
                float2 o0 = { acc[mi][ni][0] + b2.x, acc[mi][ni][1] + b2.y };
                float2 o1 = { acc[mi][ni][2] + b2.x, acc[mi][ni][3] + b2.y };
                *(float2*)(g_skip + (size_t)row * CC + col)       = o0;
                *(float2*)(g_skip + (size_t)(row + 8) * CC + col) = o1;
            }
        }
    }
}

// ---- Kernel 2: flash attention, 64-row CTA x 4 warps ----------------------
// S = tf32 single-pass (Q,K fp32-tf32); P·V = bf16 split (unchanged layout).
#define KTSTR 272                // K fp32 smem row stride bytes (68 floats)
#define KTT   (64 * KTSTR)       // 17408
#define KVSTR 144                // V smem row stride bytes (72 bf16)
#define KVT   (64 * KVSTR)       // 9216
#define XSTR2 272                // Xa smem row stride bytes (68 floats)
#define XAT2  (64 * XSTR2)       // 17408
#define ASTG2 (KTT + 2 * KVT + XAT2)  // 53248
#define NJT   (NN / 64)          // 64 j-tiles

__global__ __launch_bounds__(128, 2) void attn_mma(
    const float* __restrict__ x, const float* __restrict__ we)
{
    extern __shared__ char dsm[];
    const int tid = threadIdx.x;
    const int wid = tid >> 5;          // 0..3
    const int lane = tid & 31;
    const int h  = blockIdx.y;
    const int i0 = blockIdx.x * 64;
    const int qr = lane >> 2;          // 0..7
    const int qc = lane & 3;           // 0..3

    const uint32_t sbase = smem_u32(dsm);

    // ---- Q fragments (tf32 fp32, pre-scaled 1/8) + qe = (q/8)·we ----
    uint32_t qa[8][4];
    float qe0 = 0.f, qe1 = 0.f;
    {
        const int r0 = i0 + wid * 16 + qr;
        #pragma unroll
        for (int ks = 0; ks < 8; ks++) {
            int col = h * DD + ks * 8 + qc;
            qa[ks][0] = *(const uint32_t*)(g_qt + (size_t)r0 * CC + col);
            qa[ks][1] = *(const uint32_t*)(g_qt + (size_t)(r0 + 8) * CC + col);
            qa[ks][2] = *(const uint32_t*)(g_qt + (size_t)r0 * CC + col + 4);
            qa[ks][3] = *(const uint32_t*)(g_qt + (size_t)(r0 + 8) * CC + col + 4);
            float w0 = __ldg(we + col);
            float w4 = __ldg(we + col + 4);
            qe0 = fmaf(__uint_as_float(qa[ks][0]), w0,
                  fmaf(__uint_as_float(qa[ks][2]), w4, qe0));
            qe1 = fmaf(__uint_as_float(qa[ks][1]), w0,
                  fmaf(__uint_as_float(qa[ks][3]), w4, qe1));
        }
        qe0 += __shfl_xor_sync(0xffffffffu, qe0, 1);
        qe0 += __shfl_xor_sync(0xffffffffu, qe0, 2);
        qe1 += __shfl_xor_sync(0xffffffffu, qe1, 1);
        qe1 += __shfl_xor_sync(0xffffffffu, qe1, 2);
    }

    // stage layout: [Kt fp32 | Vh | Vl | Xa]
    auto load_stage = [&](int st, int j0) {
        const uint32_t sb = sbase + st * ASTG2;
        #pragma unroll
        for (int n = 0; n < 8; n++) {           // Kt: 1024 chunks
            int id = tid + n * 128;
            int row = id >> 4, c16 = id & 15;
            cp_async16(sb + row * KTSTR + c16 * 16,
                       g_kt + (size_t)(j0 + row) * CC + h * DD + c16 * 4);
        }
        #pragma unroll
        for (int n = 0; n < 8; n++) {           // Vh/Vl: 512 chunks each
            int id = tid + n * 128;
            int mat = id >> 9;
            int rem = id & 511;
            int row = rem >> 3, c16 = rem & 7;
            const __nv_bfloat16* src = mat ? g_vl : g_vh;
            cp_async16(sb + KTT + mat * KVT + row * KVSTR + c16 * 16,
                       src + (size_t)(j0 + row) * CC + h * DD + c16 * 8);
        }
        #pragma unroll
        for (int n = 0; n < 8; n++) {           // Xa: 1024 chunks
            int id = tid + n * 128;
            int row = id >> 4, c16 = id & 15;
            cp_async16(sb + KTT + 2 * KVT + row * XSTR2 + c16 * 16,
                       x + (size_t)(j0 + row) * NN + i0 + c16 * 4);
        }
        cp_commit();
    };

    float o[8][4];
    #pragma unroll
    for (int nd = 0; nd < 8; nd++)
        #pragma unroll
        for (int r = 0; r < 4; r++) o[nd][r] = 0.f;
    float m0 = -1e30f, m1 = -1e30f, l0 = 0.f, l1 = 0.f, sa0 = 0.f, sa1 = 0.f;

    const int vrow  = (lane & 7) + ((lane >> 3) & 1) * 8;
    const int vcol8 = ((lane >> 4) & 1) * 8;
    const int iloc0 = wid * 16 + qr;             // 0..63

    load_stage(0, 0);

    for (int jt = 0; jt < NJT; jt++) {
        if (jt + 1 < NJT) { load_stage((jt + 1) & 1, (jt + 1) * 64); cp_wait<1>(); }
        else              { cp_wait<0>(); }
        __syncthreads();

        const uint32_t sb = sbase + (jt & 1) * ASTG2;
        const float* xa = (const float*)(dsm + (size_t)(jt & 1) * ASTG2 + KTT + 2 * KVT);

        // ---- S = (Q/8)·K^T via single-pass tf32 MMA ----
        float s[8][4];
        #pragma unroll
        for (int nb = 0; nb < 8; nb++)
            #pragma unroll
            for (int r = 0; r < 4; r++) s[nb][r] = 0.f;

        #pragma unroll
        for (int ks = 0; ks < 8; ks++) {
            #pragma unroll
            for (int nb = 0; nb < 8; nb++) {
                uint32_t boff = sb + (nb * 8 + qr) * KTSTR + (ks * 8 + qc) * 4;
                uint32_t b0, b1;
                lds32(b0, boff);
                lds32(b1, boff + 16);
                mma_tf32(s[nb], qa[ks], b0, b1);
            }
        }

        // ---- edge term + tile max ----
        float tm0 = -1e30f, tm1 = -1e30f;
        #pragma unroll
        for (int nb = 0; nb < 8; nb++) {
            int j = nb * 8 + 2 * qc;
            float x00 = xa[j * 68 + iloc0];
            float x01 = xa[(j + 1) * 68 + iloc0];
            float x10 = xa[j * 68 + iloc0 + 8];
            float x11 = xa[(j + 1) * 68 + iloc0 + 8];
            s[nb][0] = fmaf(x00, qe0, s[nb][0]);
            s[nb][1] = fmaf(x01, qe0, s[nb][1]);
            s[nb][2] = fmaf(x10, qe1, s[nb][2]);
            s[nb][3] = fmaf(x11, qe1, s[nb][3]);
            tm0 = fmaxf(tm0, fmaxf(s[nb][0], s[nb][1]));
            tm1 = fmaxf(tm1, fmaxf(s[nb][2], s[nb][3]));
        }
        tm0 = fmaxf(tm0, __shfl_xor_sync(0xffffffffu, tm0, 1));
        tm0 = fmaxf(tm0, __shfl_xor_sync(0xffffffffu, tm0, 2));
        tm1 = fmaxf(tm1, __shfl_xor_sync(0xffffffffu, tm1, 1));
        tm1 = fmaxf(tm1, __shfl_xor_sync(0xffffffffu, tm1, 2));

        float m0n = fmaxf(m0, tm0), m1n = fmaxf(m1, tm1);
        float sc0 = __expf(m0 - m0n), sc1 = __expf(m1 - m1n);
        l0 *= sc0; sa0 *= sc0; l1 *= sc1; sa1 *= sc1;
        #pragma unroll
        for (int nd = 0; nd < 8; nd++) {
            o[nd][0] *= sc0; o[nd][1] *= sc0;
            o[nd][2] *= sc1; o[nd][3] *= sc1;
        }
        m0 = m0n; m1 = m1n;

        // ---- p = exp(s-m); accumulate l, sacc; overwrite s with p ----
        #pragma unroll
        for (int nb = 0; nb < 8; nb++) {
            int j = nb * 8 + 2 * qc;
            float p0 = __expf(s[nb][0] - m0);
            float p1 = __expf(s[nb][1] - m0);
            float p2 = __expf(s[nb][2] - m1);
            float p3 = __expf(s[nb][3] - m1);
            l0 += p0 + p1; l1 += p2 + p3;
            float x00 = xa[j * 68 + iloc0];
            float x01 = xa[(j + 1) * 68 + iloc0];
            float x10 = xa[j * 68 + iloc0 + 8];
            float x11 = xa[(j + 1) * 68 + iloc0 + 8];
            sa0 = fmaf(p0, x00, fmaf(p1, x01, sa0));
            sa1 = fmaf(p2, x10, fmaf(p3, x11, sa1));
            s[nb][0] = p0; s[nb][1] = p1; s[nb][2] = p2; s[nb][3] = p3;
        }

        // ---- O += P·V (bf16 split) ----
        #pragma unroll
        for (int ks = 0; ks < 4; ks++) {
            uint32_t ph[4], pl[4];
            split2(s[2 * ks][0],     s[2 * ks][1],     ph[0], pl[0]);
            split2(s[2 * ks][2],     s[2 * ks][3],     ph[1], pl[1]);
            split2(s[2 * ks + 1][0], s[2 * ks + 1][1], ph[2], pl[2]);
            split2(s[2 * ks + 1][2], s[2 * ks + 1][3], ph[3], pl[3]);
            #pragma unroll
            for (int ndp = 0; ndp < 4; ndp++) {
                uint32_t vh4[4], vl4[4];
                uint32_t off = (ks * 16 + vrow) * KVSTR + (ndp * 16 + vcol8) * 2;
                ldm_x4_t(vh4, sb + KTT + off);
                ldm_x4_t(vl4, sb + KTT + KVT + off);
                #pragma unroll
                for (int sub = 0; sub < 2; sub++) {
                    int nd = ndp * 2 + sub;
                    mma_bf16(o[nd], ph, vh4[sub * 2], vh4[sub * 2 + 1]);
                    mma_bf16(o[nd], ph, vl4[sub * 2], vl4[sub * 2 + 1]);
                    mma_bf16(o[nd], pl, vh4[sub * 2], vh4[sub * 2 + 1]);
                }
            }
        }
        __syncthreads();
    }

    // ---- epilogue: reduce l/sacc over quad, combine, write g_pre ----
    l0 += __shfl_xor_sync(0xffffffffu, l0, 1);
    l0 += __shfl_xor_sync(0xffffffffu, l0, 2);
    l1 += __shfl_xor_sync(0xffffffffu, l1, 1);
    l1 += __shfl_xor_sync(0xffffffffu, l1, 2);
    sa0 += __shfl_xor_sync(0xffffffffu, sa0, 1);
    sa0 += __shfl_xor_sync(0xffffffffu, sa0, 2);
    sa1 += __shfl_xor_sync(0xffffffffu, sa1, 1);
    sa1 += __shfl_xor_sync(0xffffffffu, sa1, 2);

    float inv0 = 1.f / l0, inv1 = 1.f / l1;
    float se0 = sa0 * inv0, se1 = sa1 * inv1;
    const int gr0 = i0 + wid * 16 + qr;
    #pragma unroll
    for (int nd = 0; nd < 8; nd++) {
        int c = h * DD + nd * 8 + 2 * qc;
        float2 wv  = *(const float2*)(we + c);
        float2 sk0 = *(const float2*)(g_skip + (size_t)gr0 * CC + c);
        float2 sk1 = *(const float2*)(g_skip + (size_t)(gr0 + 8) * CC + c);
        float2 r0, r1;
        r0.x = fmaf(o[nd][0], inv0, fmaf(se0, wv.x, sk0.x));
        r0.y = fmaf(o[nd][1], inv0, fmaf(se0, wv.y, sk0.y));
        r1.x = fmaf(o[nd][2], inv1, fmaf(se1, wv.x, sk1.x));
        r1.y = fmaf(o[nd][3], inv1, fmaf(se1, wv.y, sk1.y));
        *(float2*)(g_pre + (size_t)gr0 * CC + c)       = r0;
        *(float2*)(g_pre + (size_t)(gr0 + 8) * CC + c) = r1;
    }
}

// ---------------- Kernel 3/4: GraphNorm column stats ----------------
__global__ __launch_bounds__(128) void stats_partial()
{
    int c  = blockIdx.x * 128 + threadIdx.x;
    int r0 = blockIdx.y * 128;
    double s = 0.0, s2 = 0.0;
    for (int r = r0; r < r0 + 128; r++) {
        float v = g_pre[(size_t)r * CC + c];
        s  += (double)v;
        s2 += (double)v * (double)v;
    }
    g_psum[blockIdx.y][c] = s;
    g_psq [blockIdx.y][c] = s2;
}

__global__ __launch_bounds__(128) void stats_final(const float* __restrict__ gn_ms)
{
    int c = blockIdx.x * 128 + threadIdx.x;
    double s = 0.0, s2 = 0.0;
    #pragma unroll
    for (int p = 0; p < 32; p++) { s += g_psum[p][c]; s2 += g_psq[p][c]; }
    float mean = (float)(s * (1.0 / NN));
    float ex2  = (float)(s2 * (1.0 / NN));
    float ms   = gn_ms[c];
    float var  = ex2 - 2.f * ms * mean * mean + ms * ms * mean * mean;
    g_mean[c] = mean;
    g_rstd[c] = rsqrtf(var + EPS_GN);
}

// ---------------- Kernel 5: GraphNorm apply + per-row L2 ----------------
__global__ __launch_bounds__(128) void finalize_kernel(
    const float* __restrict__ gn_w, const float* __restrict__ gn_b,
    const float* __restrict__ gn_ms, float* __restrict__ out)
{
    int r = blockIdx.x;
    int tid = threadIdx.x;
    __shared__ float red[4];

    float vals[4];
    float ss = 0.f;
    #pragma unroll
    for (int it = 0; it < 4; it++) {
        int c = tid + it * 128;
        float v = g_pre[(size_t)r * CC + c];
        v = fmaf(gn_w[c] * g_rstd[c], v - gn_ms[c] * g_mean[c], gn_b[c]);
        vals[it] = v;
        ss += v * v;
    }
    #pragma unroll
    for (int off = 16; off; off >>= 1)
        ss += __shfl_xor_sync(0xffffffffu, ss, off);
    if ((tid & 31) == 0) red[tid >> 5] = ss;
    __syncthreads();
    float tot = red[0] + red[1] + red[2] + red[3];
    float inv = rsqrtf(tot);
    #pragma unroll
    for (int it = 0; it < 4; it++)
        out[(size_t)r * CC + tid + it * 128] = vals[it] * inv;
}

// ---------------- launch ----------------
extern "C" void kernel_launch(void* const* d_in, const int* in_sizes, int n_in,
                              void* d_out, int out_size)
{
    const float* x     = (const float*)d_in[0];
    const float* Wq    = (const float*)d_in[1];
    const float* bq    = (const float*)d_in[2];
    const float* Wk    = (const float*)d_in[3];
    const float* bk    = (const float*)d_in[4];
    const float* Wv    = (const float*)d_in[5];
    const float* bv    = (const float*)d_in[6];
    const float* we    = (const float*)d_in[7];
    const float* Wskip = (const float*)d_in[8];
    const float* bskip = (const float*)d_in[9];
    const float* gn_w  = (const float*)d_in[10];
    const float* gn_b  = (const float*)d_in[11];
    const float* gn_ms = (const float*)d_in[12];
    float* out = (float*)d_out;

    const int GEMM_SMEM = 2 * STG;       // 73728 -> 2 CTAs/SM
    cudaFuncSetAttribute(gemm_mma, cudaFuncAttributeMaxDynamicSharedMemorySize,
                         GEMM_SMEM);
    const int ATTN_SMEM = 2 * ASTG2;     // 106496 -> 2 CTAs/SM
    cudaFuncSetAttribute(attn_mma, cudaFuncAttributeMaxDynamicSharedMemorySize,
                         ATTN_SMEM);

    convert_x<<<(NN * (size_t)NN) / (256 * 4), 256>>>(x);
    convert_w<<<dim3(NN / 32, CC / 32, 2), dim3(32, 8)>>>(Wq, Wk, 0);
    convert_w<<<dim3(NN / 32, CC / 32, 2), dim3(32, 8)>>>(Wv, Wskip, 2);

    gemm_mma<<<dim3(NN / 128, CC / 128, 4), 128, GEMM_SMEM>>>(bq, bk, bv, bskip);

    attn_mma<<<dim3(NN / 64, HH), 128, ATTN_SMEM>>>(x, we);

    stats_partial<<<dim3(4, 32), 128>>>();
    stats_final<<<4, 128>>>(gn_ms);
    finalize_kernel<<<NN, 128>>>(gn_w, gn_b, gn_ms, out);
}

// round 15
// speedup vs baseline: 1.0792x; 1.0235x over previous
#include <cuda_runtime.h>
#include <cuda_bf16.h>
#include <cstdint>

// Problem constants
#define NN   4096
#define HH   8
#define CC   512
#define DD   64
#define EPS_GN 1e-5f

// ---------------- scratch (device globals; no allocation) ----------------
__device__ float g_wt[(size_t)4 * CC * NN];      // tf32-rounded W^T [z][c][k]
__device__ float g_qt[(size_t)NN * CC];          // tf32 Q (pre-scaled 1/8)
__device__ float g_kt[(size_t)NN * CC];          // tf32 K
__device__ __nv_bfloat16 g_vh[(size_t)NN * CC];
__device__ __nv_bfloat16 g_vl[(size_t)NN * CC];
__device__ float g_skip[NN * CC];
__device__ float g_pre[NN * CC];
__device__ double g_psum[32][CC];
__device__ double g_psq[32][CC];
__device__ float g_mean[CC];
__device__ float g_rstd[CC];

// ---------------- PTX helpers (baseline ISA only) ----------------
__device__ __forceinline__ uint32_t smem_u32(const void* p) {
    uint32_t a;
    asm("{ .reg .u64 t; cvta.to.shared.u64 t, %1; cvt.u32.u64 %0, t; }"
        : "=r"(a) : "l"(p));
    return a;
}
__device__ __forceinline__ void cp_async16(uint32_t dst, const void* src) {
    asm volatile("cp.async.cg.shared.global [%0], [%1], 16;"
                 :: "r"(dst), "l"(src) : "memory");
}
__device__ __forceinline__ void cp_commit() {
    asm volatile("cp.async.commit_group;" ::: "memory");
}
template <int N>
__device__ __forceinline__ void cp_wait() {
    asm volatile("cp.async.wait_group %0;" :: "n"(N) : "memory");
}
__device__ __forceinline__ void ldm_x4_t(uint32_t* r, uint32_t addr) {
    asm volatile("ldmatrix.sync.aligned.m8n8.x4.trans.shared.b16 {%0,%1,%2,%3}, [%4];"
                 : "=r"(r[0]), "=r"(r[1]), "=r"(r[2]), "=r"(r[3]) : "r"(addr));
}
__device__ __forceinline__ void lds32(uint32_t& v, uint32_t addr) {
    asm volatile("ld.shared.b32 %0, [%1];" : "=r"(v) : "r"(addr));
}
__device__ __forceinline__ void mma_bf16(float* d, const uint32_t* a,
                                         uint32_t b0, uint32_t b1) {
    asm volatile(
        "mma.sync.aligned.m16n8k16.row.col.f32.bf16.bf16.f32 "
        "{%0,%1,%2,%3}, {%4,%5,%6,%7}, {%8,%9}, {%0,%1,%2,%3};"
        : "+f"(d[0]), "+f"(d[1]), "+f"(d[2]), "+f"(d[3])
        : "r"(a[0]), "r"(a[1]), "r"(a[2]), "r"(a[3]), "r"(b0), "r"(b1));
}
__device__ __forceinline__ void mma_tf32(float* d, const uint32_t* a,
                                         uint32_t b0, uint32_t b1) {
    asm volatile(
        "mma.sync.aligned.m16n8k8.row.col.f32.tf32.tf32.f32 "
        "{%0,%1,%2,%3}, {%4,%5,%6,%7}, {%8,%9}, {%0,%1,%2,%3};"
        : "+f"(d[0]), "+f"(d[1]), "+f"(d[2]), "+f"(d[3])
        : "r"(a[0]), "r"(a[1]), "r"(a[2]), "r"(a[3]), "r"(b0), "r"(b1));
}
__device__ __forceinline__ uint32_t to_tf32(float f) {
    uint32_t r;
    asm("cvt.rna.tf32.f32 %0, %1;" : "=r"(r) : "f"(f));
    return r;
}
__device__ __forceinline__ void split2(float a, float b, uint32_t& hi, uint32_t& lo) {
    __nv_bfloat16 ha = __float2bfloat16_rn(a), hb = __float2bfloat16_rn(b);
    __nv_bfloat16 la = __float2bfloat16_rn(a - __bfloat162float(ha));
    __nv_bfloat16 lb = __float2bfloat16_rn(b - __bfloat162float(hb));
    __nv_bfloat162 H(ha, hb), L(la, lb);
    hi = *(uint32_t*)&H;
    lo = *(uint32_t*)&L;
}

// ---------------- conversion kernel ----------------
// transpose + tf32-round W: Wt[z][c][k] = W[z][k][c]; zbase selects pair
__global__ __launch_bounds__(256) void convert_w(
    const float* __restrict__ W0, const float* __restrict__ W1, int zbase)
{
    const float* W = blockIdx.z ? W1 : W0;
    __shared__ float t[32][33];
    int k0 = blockIdx.x * 32, c0 = blockIdx.y * 32;
    int tx = threadIdx.x, ty = threadIdx.y;  // 32 x 8
    #pragma unroll
    for (int i = 0; i < 4; i++)
        t[ty + i * 8][tx] = W[(size_t)(k0 + ty + i * 8) * CC + c0 + tx];
    __syncthreads();
    #pragma unroll
    for (int i = 0; i < 4; i++) {
        uint32_t v = to_tf32(t[tx][ty + i * 8]);
        size_t o = ((size_t)(zbase + blockIdx.z) * CC + c0 + ty + i * 8) * NN + k0 + tx;
        *(uint32_t*)(g_wt + o) = v;
    }
}

// ---- Kernel: tf32 GEMM, CTA 128x128, 4 warps (64x64 warp tile), 2 CTAs/SM --
// A operand streams raw fp32 x (tf32 MMA reads top 19 bits — implicit trunc).
#define KCH 32
#define AROWB 144                 // 36 floats row stride
#define TILE_A (128 * AROWB)      // 18432
#define TILE_B2 (128 * AROWB)     // 18432
#define STG (TILE_A + TILE_B2)    // 36864
#define NCH (NN / KCH)            // 128

__global__ __launch_bounds__(128, 2) void gemm_mma(
    const float* __restrict__ x,
    const float* __restrict__ bq, const float* __restrict__ bk,
    const float* __restrict__ bv, const float* __restrict__ bs)
{
    extern __shared__ char dsm[];
    const int tid = threadIdx.x;
    const int wid = tid >> 5;      // 0..3
    const int lane = tid & 31;
    const int z = blockIdx.z;
    const int bm = blockIdx.x * 128;
    const int bn = blockIdx.y * 128;

    const float* bias;
    switch (z) {
        case 0:  bias = bq; break;
        case 1:  bias = bk; break;
        case 2:  bias = bv; break;
        default: bias = bs; break;
    }

    const uint32_t sbase = smem_u32(dsm);
    const float* srcA = x + (size_t)bm * NN;
    const float* srcB = g_wt + ((size_t)z * CC + bn) * NN;

    // stage layout: [A 128x144B | B 128x144B]
    auto load_stage = [&](int stage, int k0) {
        const uint32_t sb = sbase + stage * STG;
        #pragma unroll
        for (int t = 0; t < 16; t++) {
            int idx = tid + t * 128;              // 0..2047
            if (idx < 1024) {                     // A: 1024 float4
                int row = idx >> 3, c4 = idx & 7;
                cp_async16(sb + row * AROWB + c4 * 16,
                           srcA + (size_t)row * NN + k0 + c4 * 4);
            } else {                              // B: 1024 float4
                int bi = idx - 1024;
                int row = bi >> 3, c4 = bi & 7;
                cp_async16(sb + TILE_A + row * AROWB + c4 * 16,
                           srcB + (size_t)row * NN + k0 + c4 * 4);
            }
        }
        cp_commit();
    };

    float acc[4][8][4];
    #pragma unroll
    for (int i = 0; i < 4; i++)
        #pragma unroll
        for (int j = 0; j < 8; j++)
            #pragma unroll
            for (int r = 0; r < 4; r++) acc[i][j][r] = 0.f;

    const int wm = wid >> 1;       // 0..1 -> m offset wm*64
    const int wn = wid & 1;        // 0..1 -> n offset wn*64
    const int qr = lane >> 2;      // 0..7
    const int qc = lane & 3;       // 0..3

    load_stage(0, 0);

    for (int ch = 0; ch < NCH; ch++) {
        if (ch + 1 < NCH) { load_stage((ch + 1) & 1, (ch + 1) * KCH); cp_wait<1>(); }
        else              { cp_wait<0>(); }
        __syncthreads();

        const uint32_t sA = sbase + (ch & 1) * STG;
        const uint32_t sB = sA + TILE_A;

        #pragma unroll
        for (int ks8 = 0; ks8 < 4; ks8++) {
            const int kb = ks8 * 8;
            uint32_t a[4][4];
            #pragma unroll
            for (int mi = 0; mi < 4; mi++) {
                int row = wm * 64 + mi * 16 + qr;
                uint32_t off = sA + row * AROWB + (kb + qc) * 4;
                lds32(a[mi][0], off);
                lds32(a[mi][2], off + 16);
                lds32(a[mi][1], off + 8 * AROWB);
                lds32(a[mi][3], off + 8 * AROWB + 16);
            }
            #pragma unroll
            for (int ni = 0; ni < 8; ni++) {
                int nrow = wn * 64 + ni * 8 + qr;
                uint32_t boff = sB + nrow * AROWB + (kb + qc) * 4;
                uint32_t b0, b1;
                lds32(b0, boff);
                lds32(b1, boff + 16);
                #pragma unroll
                for (int mi = 0; mi < 4; mi++)
                    mma_tf32(acc[mi][ni], a[mi], b0, b1);
            }
        }
        __syncthreads();
    }

    // epilogue: z==0 -> tf32 fp32 Q (scaled 1/8); z==1 -> tf32 fp32 K;
    //           z==2 -> bf16 hi/lo V;       z==3 -> fp32 skip
    if (z < 2) {
        float* Ot = z ? g_kt : g_qt;
        const float sc = (z == 0) ? 0.125f : 1.0f;
        #pragma unroll
        for (int mi = 0; mi < 4; mi++) {
            int row = bm + wm * 64 + mi * 16 + (lane >> 2);
            #pragma unroll
            for (int ni = 0; ni < 8; ni++) {
                int col = bn + wn * 64 + ni * 8 + (lane & 3) * 2;
                float2 b2 = *(const float2*)(bias + col);
                uint2 o0, o1;
                o0.x = to_tf32((acc[mi][ni][0] + b2.x) * sc);
                o0.y = to_tf32((acc[mi][ni][1] + b2.y) * sc);
                o1.x = to_tf32((acc[mi][ni][2] + b2.x) * sc);
                o1.y = to_tf32((acc[mi][ni][3] + b2.y) * sc);
                *(uint2*)(Ot + (size_t)row * CC + col)       = o0;
                *(uint2*)(Ot + (size_t)(row + 8) * CC + col) = o1;
            }
        }
    } else if (z == 2) {
        #pragma unroll
        for (int mi = 0; mi < 4; mi++) {
            int row = bm + wm * 64 + mi * 16 + (lane >> 2);
            #pragma unroll
            for (int ni = 0; ni < 8; ni++) {
                int col = bn + wn * 64 + ni * 8 + (lane & 3) * 2;
                float2 b2 = *(const float2*)(bias + col);
                float v00 = acc[mi][ni][0] + b2.x;
                float v01 = acc[mi][ni][1] + b2.y;
                float v10 = acc[mi][ni][2] + b2.x;
                float v11 = acc[mi][ni][3] + b2.y;
                uint32_t h0, l0, h1, l1;
                split2(v00, v01, h0, l0);
                split2(v10, v11, h1, l1);
                *(uint32_t*)(g_vh + (size_t)row * CC + col)       = h0;
                *(uint32_t*)(g_vl + (size_t)row * CC + col)       = l0;
                *(uint32_t*)(g_vh + (size_t)(row + 8) * CC + col) = h1;
                *(uint32_t*)(g_vl + (size_t)(row + 8) * CC + col) = l1;
            }
        }
    } else {
        #pragma unroll
        for (int mi = 0; mi < 4; mi++) {
            int row = bm + wm * 64 + mi * 16 + (lane >> 2);
            #pragma unroll
            for (int ni = 0; ni < 8; ni++) {
                int col = bn + wn * 64 + ni * 8 + (lane & 3) * 2;
                float2 b2 = *(const float2*)(bias + col);
                float2 o0 = { acc[mi][ni][0] + b2.x, acc[mi][ni][1] + b2.y };
                float2 o1 = { acc[mi][ni][2] + b2.x, acc[mi][ni][3] + b2.y };
                *(float2*)(g_skip + (size_t)row * CC + col)       = o0;
                *(float2*)(g_skip + (size_t)(row + 8) * CC + col) = o1;
            }
        }
    }
}

// ---- Kernel 2: flash attention, 64-row CTA x 4 warps ----------------------
// S = tf32 single-pass (Q,K fp32-tf32); P·V = bf16 split.
#define KTSTR 272                // K fp32 smem row stride bytes (68 floats)
#define KTT   (64 * KTSTR)       // 17408
#define KVSTR 144                // V smem row stride bytes (72 bf16)
#define KVT   (64 * KVSTR)       // 9216
#define XSTR2 272                // Xa smem row stride bytes (68 floats)
#define XAT2  (64 * XSTR2)       // 17408
#define ASTG2 (KTT + 2 * KVT + XAT2)  // 53248
#define NJT   (NN / 64)          // 64 j-tiles

__global__ __launch_bounds__(128, 2) void attn_mma(
    const float* __restrict__ x, const float* __restrict__ we)
{
    extern __shared__ char dsm[];
    const int tid = threadIdx.x;
    const int wid = tid >> 5;          // 0..3
    const int lane = tid & 31;
    const int h  = blockIdx.y;
    const int i0 = blockIdx.x * 64;
    const int qr = lane >> 2;          // 0..7
    const int qc = lane & 3;           // 0..3

    const uint32_t sbase = smem_u32(dsm);

    // ---- Q fragments (tf32 fp32, pre-scaled 1/8) + qe = (q/8)·we ----
    uint32_t qa[8][4];
    float qe0 = 0.f, qe1 = 0.f;
    {
        const int r0 = i0 + wid * 16 + qr;
        #pragma unroll
        for (int ks = 0; ks < 8; ks++) {
            int col = h * DD + ks * 8 + qc;
            qa[ks][0] = *(const uint32_t*)(g_qt + (size_t)r0 * CC + col);
            qa[ks][1] = *(const uint32_t*)(g_qt + (size_t)(r0 + 8) * CC + col);
            qa[ks][2] = *(const uint32_t*)(g_qt + (size_t)r0 * CC + col + 4);
            qa[ks][3] = *(const uint32_t*)(g_qt + (size_t)(r0 + 8) * CC + col + 4);
            float w0 = __ldg(we + col);
            float w4 = __ldg(we + col + 4);
            qe0 = fmaf(__uint_as_float(qa[ks][0]), w0,
                  fmaf(__uint_as_float(qa[ks][2]), w4, qe0));
            qe1 = fmaf(__uint_as_float(qa[ks][1]), w0,
                  fmaf(__uint_as_float(qa[ks][3]), w4, qe1));
        }
        qe0 += __shfl_xor_sync(0xffffffffu, qe0, 1);
        qe0 += __shfl_xor_sync(0xffffffffu, qe0, 2);
        qe1 += __shfl_xor_sync(0xffffffffu, qe1, 1);
        qe1 += __shfl_xor_sync(0xffffffffu, qe1, 2);
    }

    // stage layout: [Kt fp32 | Vh | Vl | Xa]
    auto load_stage = [&](int st, int j0) {
        const uint32_t sb = sbase + st * ASTG2;
        #pragma unroll
        for (int n = 0; n < 8; n++) {           // Kt: 1024 chunks
            int id = tid + n * 128;
            int row = id >> 4, c16 = id & 15;
            cp_async16(sb + row * KTSTR + c16 * 16,
                       g_kt + (size_t)(j0 + row) * CC + h * DD + c16 * 4);
        }
        #pragma unroll
        for (int n = 0; n < 8; n++) {           // Vh/Vl: 512 chunks each
            int id = tid + n * 128;
            int mat = id >> 9;
            int rem = id & 511;
            int row = rem >> 3, c16 = rem & 7;
            const __nv_bfloat16* src = mat ? g_vl : g_vh;
            cp_async16(sb + KTT + mat * KVT + row * KVSTR + c16 * 16,
                       src + (size_t)(j0 + row) * CC + h * DD + c16 * 8);
        }
        #pragma unroll
        for (int n = 0; n < 8; n++) {           // Xa: 1024 chunks
            int id = tid + n * 128;
            int row = id >> 4, c16 = id & 15;
            cp_async16(sb + KTT + 2 * KVT + row * XSTR2 + c16 * 16,
                       x + (size_t)(j0 + row) * NN + i0 + c16 * 4);
        }
        cp_commit();
    };

    float o[8][4];
    #pragma unroll
    for (int nd = 0; nd < 8; nd++)
        #pragma unroll
        for (int r = 0; r < 4; r++) o[nd][r] = 0.f;
    float m0 = -1e30f, m1 = -1e30f, l0 = 0.f, l1 = 0.f, sa0 = 0.f, sa1 = 0.f;

    const int vrow  = (lane & 7) + ((lane >> 3) & 1) * 8;
    const int vcol8 = ((lane >> 4) & 1) * 8;
    const int iloc0 = wid * 16 + qr;             // 0..63

    load_stage(0, 0);

    for (int jt = 0; jt < NJT; jt++) {
        if (jt + 1 < NJT) { load_stage((jt + 1) & 1, (jt + 1) * 64); cp_wait<1>(); }
        else              { cp_wait<0>(); }
        __syncthreads();

        const uint32_t sb = sbase + (jt & 1) * ASTG2;
        const float* xa = (const float*)(dsm + (size_t)(jt & 1) * ASTG2 + KTT + 2 * KVT);

        // ---- S = (Q/8)·K^T via single-pass tf32 MMA ----
        float s[8][4];
        #pragma unroll
        for (int nb = 0; nb < 8; nb++)
            #pragma unroll
            for (int r = 0; r < 4; r++) s[nb][r] = 0.f;

        #pragma unroll
        for (int ks = 0; ks < 8; ks++) {
            #pragma unroll
            for (int nb = 0; nb < 8; nb++) {
                uint32_t boff = sb + (nb * 8 + qr) * KTSTR + (ks * 8 + qc) * 4;
                uint32_t b0, b1;
                lds32(b0, boff);
                lds32(b1, boff + 16);
                mma_tf32(s[nb], qa[ks], b0, b1);
            }
        }

        // ---- edge term + tile max ----
        float tm0 = -1e30f, tm1 = -1e30f;
        #pragma unroll
        for (int nb = 0; nb < 8; nb++) {
            int j = nb * 8 + 2 * qc;
            float x00 = xa[j * 68 + iloc0];
            float x01 = xa[(j + 1) * 68 + iloc0];
            float x10 = xa[j * 68 + iloc0 + 8];
            float x11 = xa[(j + 1) * 68 + iloc0 + 8];
            s[nb][0] = fmaf(x00, qe0, s[nb][0]);
            s[nb][1] = fmaf(x01, qe0, s[nb][1]);
            s[nb][2] = fmaf(x10, qe1, s[nb][2]);
            s[nb][3] = fmaf(x11, qe1, s[nb][3]);
            tm0 = fmaxf(tm0, fmaxf(s[nb][0], s[nb][1]));
            tm1 = fmaxf(tm1, fmaxf(s[nb][2], s[nb][3]));
        }
        tm0 = fmaxf(tm0, __shfl_xor_sync(0xffffffffu, tm0, 1));
        tm0 = fmaxf(tm0, __shfl_xor_sync(0xffffffffu, tm0, 2));
        tm1 = fmaxf(tm1, __shfl_xor_sync(0xffffffffu, tm1, 1));
        tm1 = fmaxf(tm1, __shfl_xor_sync(0xffffffffu, tm1, 2));

        float m0n = fmaxf(m0, tm0), m1n = fmaxf(m1, tm1);
        float sc0 = __expf(m0 - m0n), sc1 = __expf(m1 - m1n);
        l0 *= sc0; sa0 *= sc0; l1 *= sc1; sa1 *= sc1;
        #pragma unroll
        for (int nd = 0; nd < 8; nd++) {
            o[nd][0] *= sc0; o[nd][1] *= sc0;
            o[nd][2] *= sc1; o[nd][3] *= sc1;
        }
        m0 = m0n; m1 = m1n;

        // ---- p = exp(s-m); accumulate l, sacc; overwrite s with p ----
        #pragma unroll
        for (int nb = 0; nb < 8; nb++) {
            int j = nb * 8 + 2 * qc;
            float p0 = __expf(s[nb][0] - m0);
            float p1 = __expf(s[nb][1] - m0);
            float p2 = __expf(s[nb][2] - m1);
            float p3 = __expf(s[nb][3] - m1);
            l0 += p0 + p1; l1 += p2 + p3;
            float x00 = xa[j * 68 + iloc0];
            float x01 = xa[(j + 1) * 68 + iloc0];
            float x10 = xa[j * 68 + iloc0 + 8];
            float x11 = xa[(j + 1) * 68 + iloc0 + 8];
            sa0 = fmaf(p0, x00, fmaf(p1, x01, sa0));
            sa1 = fmaf(p2, x10, fmaf(p3, x11, sa1));
            s[nb][0] = p0; s[nb][1] = p1; s[nb][2] = p2; s[nb][3] = p3;
        }

        // ---- O += P·V (bf16 split) ----
        #pragma unroll
        for (int ks = 0; ks < 4; ks++) {
            uint32_t ph[4], pl[4];
            split2(s[2 * ks][0],     s[2 * ks][1],     ph[0], pl[0]);
            split2(s[2 * ks][2],     s[2 * ks][3],     ph[1], pl[1]);
            split2(s[2 * ks + 1][0], s[2 * ks + 1][1], ph[2], pl[2]);
            split2(s[2 * ks + 1][2], s[2 * ks + 1][3], ph[3], pl[3]);
            #pragma unroll
            for (int ndp = 0; ndp < 4; ndp++) {
                uint32_t vh4[4], vl4[4];
                uint32_t off = (ks * 16 + vrow) * KVSTR + (ndp * 16 + vcol8) * 2;
                ldm_x4_t(vh4, sb + KTT + off);
                ldm_x4_t(vl4, sb + KTT + KVT + off);
                #pragma unroll
                for (int sub = 0; sub < 2; sub++) {
                    int nd = ndp * 2 + sub;
                    mma_bf16(o[nd], ph, vh4[sub * 2], vh4[sub * 2 + 1]);
                    mma_bf16(o[nd], ph, vl4[sub * 2], vl4[sub * 2 + 1]);
                    mma_bf16(o[nd], pl, vh4[sub * 2], vh4[sub * 2 + 1]);
                }
            }
        }
        __syncthreads();
    }

    // ---- epilogue: reduce l/sacc over quad, combine, write g_pre ----
    l0 += __shfl_xor_sync(0xffffffffu, l0, 1);
    l0 += __shfl_xor_sync(0xffffffffu, l0, 2);
    l1 += __shfl_xor_sync(0xffffffffu, l1, 1);
    l1 += __shfl_xor_sync(0xffffffffu, l1, 2);
    sa0 += __shfl_xor_sync(0xffffffffu, sa0, 1);
    sa0 += __shfl_xor_sync(0xffffffffu, sa0, 2);
    sa1 += __shfl_xor_sync(0xffffffffu, sa1, 1);
    sa1 += __shfl_xor_sync(0xffffffffu, sa1, 2);

    float inv0 = 1.f / l0, inv1 = 1.f / l1;
    float se0 = sa0 * inv0, se1 = sa1 * inv1;
    const int gr0 = i0 + wid * 16 + qr;
    #pragma unroll
    for (int nd = 0; nd < 8; nd++) {
        int c = h * DD + nd * 8 + 2 * qc;
        float2 wv  = *(const float2*)(we + c);
        float2 sk0 = *(const float2*)(g_skip + (size_t)gr0 * CC + c);
        float2 sk1 = *(const float2*)(g_skip + (size_t)(gr0 + 8) * CC + c);
        float2 r0, r1;
        r0.x = fmaf(o[nd][0], inv0, fmaf(se0, wv.x, sk0.x));
        r0.y = fmaf(o[nd][1], inv0, fmaf(se0, wv.y, sk0.y));
        r1.x = fmaf(o[nd][2], inv1, fmaf(se1, wv.x, sk1.x));
        r1.y = fmaf(o[nd][3], inv1, fmaf(se1, wv.y, sk1.y));
        *(float2*)(g_pre + (size_t)gr0 * CC + c)       = r0;
        *(float2*)(g_pre + (size_t)(gr0 + 8) * CC + c) = r1;
    }
}

// ---------------- Kernel 3/4: GraphNorm column stats ----------------
__global__ __launch_bounds__(128) void stats_partial()
{
    int c  = blockIdx.x * 128 + threadIdx.x;
    int r0 = blockIdx.y * 128;
    double s = 0.0, s2 = 0.0;
    for (int r = r0; r < r0 + 128; r++) {
        float v = g_pre[(size_t)r * CC + c];
        s  += (double)v;
        s2 += (double)v * (double)v;
    }
    g_psum[blockIdx.y][c] = s;
    g_psq [blockIdx.y][c] = s2;
}

__global__ __launch_bounds__(128) void stats_final(const float* __restrict__ gn_ms)
{
    int c = blockIdx.x * 128 + threadIdx.x;
    double s = 0.0, s2 = 0.0;
    #pragma unroll
    for (int p = 0; p < 32; p++) { s += g_psum[p][c]; s2 += g_psq[p][c]; }
    float mean = (float)(s * (1.0 / NN));
    float ex2  = (float)(s2 * (1.0 / NN));
    float ms   = gn_ms[c];
    float var  = ex2 - 2.f * ms * mean * mean + ms * ms * mean * mean;
    g_mean[c] = mean;
    g_rstd[c] = rsqrtf(var + EPS_GN);
}

// ---------------- Kernel 5: GraphNorm apply + per-row L2 ----------------
__global__ __launch_bounds__(128) void finalize_kernel(
    const float* __restrict__ gn_w, const float* __restrict__ gn_b,
    const float* __restrict__ gn_ms, float* __restrict__ out)
{
    int r = blockIdx.x;
    int tid = threadIdx.x;
    __shared__ float red[4];

    float vals[4];
    float ss = 0.f;
    #pragma unroll
    for (int it = 0; it < 4; it++) {
        int c = tid + it * 128;
        float v = g_pre[(size_t)r * CC + c];
        v = fmaf(gn_w[c] * g_rstd[c], v - gn_ms[c] * g_mean[c], gn_b[c]);
        vals[it] = v;
        ss += v * v;
    }
    #pragma unroll
    for (int off = 16; off; off >>= 1)
        ss += __shfl_xor_sync(0xffffffffu, ss, off);
    if ((tid & 31) == 0) red[tid >> 5] = ss;
    __syncthreads();
    float tot = red[0] + red[1] + red[2] + red[3];
    float inv = rsqrtf(tot);
    #pragma unroll
    for (int it = 0; it < 4; it++)
        out[(size_t)r * CC + tid + it * 128] = vals[it] * inv;
}

// ---------------- launch ----------------
extern "C" void kernel_launch(void* const* d_in, const int* in_sizes, int n_in,
                              void* d_out, int out_size)
{
    const float* x     = (const float*)d_in[0];
    const float* Wq    = (const float*)d_in[1];
    const float* bq    = (const float*)d_in[2];
    const float* Wk    = (const float*)d_in[3];
    const float* bk    = (const float*)d_in[4];
    const float* Wv    = (const float*)d_in[5];
    const float* bv    = (const float*)d_in[6];
    const float* we    = (const float*)d_in[7];
    const float* Wskip = (const float*)d_in[8];
    const float* bskip = (const float*)d_in[9];
    const float* gn_w  = (const float*)d_in[10];
    const float* gn_b  = (const float*)d_in[11];
    const float* gn_ms = (const float*)d_in[12];
    float* out = (float*)d_out;

    const int GEMM_SMEM = 2 * STG;       // 73728 -> 2 CTAs/SM
    cudaFuncSetAttribute(gemm_mma, cudaFuncAttributeMaxDynamicSharedMemorySize,
                         GEMM_SMEM);
    const int ATTN_SMEM = 2 * ASTG2;     // 106496 -> 2 CTAs/SM
    cudaFuncSetAttribute(attn_mma, cudaFuncAttributeMaxDynamicSharedMemorySize,
                         ATTN_SMEM);

    convert_w<<<dim3(NN / 32, CC / 32, 2), dim3(32, 8)>>>(Wq, Wk, 0);
    convert_w<<<dim3(NN / 32, CC / 32, 2), dim3(32, 8)>>>(Wv, Wskip, 2);

    gemm_mma<<<dim3(NN / 128, CC / 128, 4), 128, GEMM_SMEM>>>(x, bq, bk, bv, bskip);

    attn_mma<<<dim3(NN / 64, HH), 128, ATTN_SMEM>>>(x, we);   // launch #4 -> profiled

    stats_partial<<<dim3(4, 32), 128>>>();
    stats_final<<<4, 128>>>(gn_ms);
    finalize_kernel<<<NN, 128>>>(gn_w, gn_b, gn_ms, out);
}

// round 16
// speedup vs baseline: 1.2412x; 1.1500x over previous
#include <cuda_runtime.h>
#include <cuda_bf16.h>
#include <cstdint>

// Problem constants
#define NN   4096
#define HH   8
#define CC   512
#define DD   64
#define EPS_GN 1e-5f

// ---------------- scratch (device globals; no allocation) ----------------
__device__ float g_wt[(size_t)4 * CC * NN];      // tf32-rounded W^T [z][c][k]
__device__ float g_qt[(size_t)NN * CC];          // tf32 Q (pre-scaled 1/8)
__device__ float g_kt[(size_t)NN * CC];          // tf32 K
__device__ __nv_bfloat16 g_v[(size_t)NN * CC];   // bf16 V (single copy)
__device__ float g_skip[NN * CC];
__device__ float g_pre[NN * CC];
__device__ double g_psum[32][CC];
__device__ double g_psq[32][CC];
__device__ float g_mean[CC];
__device__ float g_rstd[CC];

// ---------------- PTX helpers (baseline ISA only) ----------------
__device__ __forceinline__ uint32_t smem_u32(const void* p) {
    uint32_t a;
    asm("{ .reg .u64 t; cvta.to.shared.u64 t, %1; cvt.u32.u64 %0, t; }"
        : "=r"(a) : "l"(p));
    return a;
}
__device__ __forceinline__ void cp_async16(uint32_t dst, const void* src) {
    asm volatile("cp.async.cg.shared.global [%0], [%1], 16;"
                 :: "r"(dst), "l"(src) : "memory");
}
__device__ __forceinline__ void cp_commit() {
    asm volatile("cp.async.commit_group;" ::: "memory");
}
template <int N>
__device__ __forceinline__ void cp_wait() {
    asm volatile("cp.async.wait_group %0;" :: "n"(N) : "memory");
}
__device__ __forceinline__ void ldm_x4_t(uint32_t* r, uint32_t addr) {
    asm volatile("ldmatrix.sync.aligned.m8n8.x4.trans.shared.b16 {%0,%1,%2,%3}, [%4];"
                 : "=r"(r[0]), "=r"(r[1]), "=r"(r[2]), "=r"(r[3]) : "r"(addr));
}
__device__ __forceinline__ void lds32(uint32_t& v, uint32_t addr) {
    asm volatile("ld.shared.b32 %0, [%1];" : "=r"(v) : "r"(addr));
}
__device__ __forceinline__ void mma_bf16(float* d, const uint32_t* a,
                                         uint32_t b0, uint32_t b1) {
    asm volatile(
        "mma.sync.aligned.m16n8k16.row.col.f32.bf16.bf16.f32 "
        "{%0,%1,%2,%3}, {%4,%5,%6,%7}, {%8,%9}, {%0,%1,%2,%3};"
        : "+f"(d[0]), "+f"(d[1]), "+f"(d[2]), "+f"(d[3])
        : "r"(a[0]), "r"(a[1]), "r"(a[2]), "r"(a[3]), "r"(b0), "r"(b1));
}
__device__ __forceinline__ void mma_tf32(float* d, const uint32_t* a,
                                         uint32_t b0, uint32_t b1) {
    asm volatile(
        "mma.sync.aligned.m16n8k8.row.col.f32.tf32.tf32.f32 "
        "{%0,%1,%2,%3}, {%4,%5,%6,%7}, {%8,%9}, {%0,%1,%2,%3};"
        : "+f"(d[0]), "+f"(d[1]), "+f"(d[2]), "+f"(d[3])
        : "r"(a[0]), "r"(a[1]), "r"(a[2]), "r"(a[3]), "r"(b0), "r"(b1));
}
__device__ __forceinline__ uint32_t to_tf32(float f) {
    uint32_t r;
    asm("cvt.rna.tf32.f32 %0, %1;" : "=r"(r) : "f"(f));
    return r;
}
// pack2(a,b) -> bf16x2 {lo=a, hi=b} (rn)
__device__ __forceinline__ uint32_t pack2(float a, float b) {
    uint32_t r;
    asm("cvt.rn.bf16x2.f32 %0, %1, %2;" : "=r"(r) : "f"(b), "f"(a));
    return r;
}

// ---------------- conversion kernel ----------------
// transpose + tf32-round W: Wt[z][c][k] = W[z][k][c]; zbase selects pair
__global__ __launch_bounds__(256) void convert_w(
    const float* __restrict__ W0, const float* __restrict__ W1, int zbase)
{
    const float* W = blockIdx.z ? W1 : W0;
    __shared__ float t[32][33];
    int k0 = blockIdx.x * 32, c0 = blockIdx.y * 32;
    int tx = threadIdx.x, ty = threadIdx.y;  // 32 x 8
    #pragma unroll
    for (int i = 0; i < 4; i++)
        t[ty + i * 8][tx] = W[(size_t)(k0 + ty + i * 8) * CC + c0 + tx];
    __syncthreads();
    #pragma unroll
    for (int i = 0; i < 4; i++) {
        uint32_t v = to_tf32(t[tx][ty + i * 8]);
        size_t o = ((size_t)(zbase + blockIdx.z) * CC + c0 + ty + i * 8) * NN + k0 + tx;
        *(uint32_t*)(g_wt + o) = v;
    }
}

// ---- Kernel: tf32 GEMM, CTA 128x128, 4 warps (64x64 warp tile), 2 CTAs/SM --
// A operand streams raw fp32 x (tf32 MMA reads top 19 bits — implicit trunc).
#define KCH 32
#define AROWB 144                 // 36 floats row stride
#define TILE_A (128 * AROWB)      // 18432
#define TILE_B2 (128 * AROWB)     // 18432
#define STG (TILE_A + TILE_B2)    // 36864
#define NCH (NN / KCH)            // 128

__global__ __launch_bounds__(128, 2) void gemm_mma(
    const float* __restrict__ x,
    const float* __restrict__ bq, const float* __restrict__ bk,
    const float* __restrict__ bv, const float* __restrict__ bs)
{
    extern __shared__ char dsm[];
    const int tid = threadIdx.x;
    const int wid = tid >> 5;      // 0..3
    const int lane = tid & 31;
    const int z = blockIdx.z;
    const int bm = blockIdx.x * 128;
    const int bn = blockIdx.y * 128;

    const float* bias;
    switch (z) {
        case 0:  bias = bq; break;
        case 1:  bias = bk; break;
        case 2:  bias = bv; break;
        default: bias = bs; break;
    }

    const uint32_t sbase = smem_u32(dsm);
    const float* srcA = x + (size_t)bm * NN;
    const float* srcB = g_wt + ((size_t)z * CC + bn) * NN;

    // stage layout: [A 128x144B | B 128x144B]
    auto load_stage = [&](int stage, int k0) {
        const uint32_t sb = sbase + stage * STG;
        #pragma unroll
        for (int t = 0; t < 16; t++) {
            int idx = tid + t * 128;              // 0..2047
            if (idx < 1024) {                     // A: 1024 float4
                int row = idx >> 3, c4 = idx & 7;
                cp_async16(sb + row * AROWB + c4 * 16,
                           srcA + (size_t)row * NN + k0 + c4 * 4);
            } else {                              // B: 1024 float4
                int bi = idx - 1024;
                int row = bi >> 3, c4 = bi & 7;
                cp_async16(sb + TILE_A + row * AROWB + c4 * 16,
                           srcB + (size_t)row * NN + k0 + c4 * 4);
            }
        }
        cp_commit();
    };

    float acc[4][8][4];
    #pragma unroll
    for (int i = 0; i < 4; i++)
        #pragma unroll
        for (int j = 0; j < 8; j++)
            #pragma unroll
            for (int r = 0; r < 4; r++) acc[i][j][r] = 0.f;

    const int wm = wid >> 1;       // 0..1 -> m offset wm*64
    const int wn = wid & 1;        // 0..1 -> n offset wn*64
    const int qr = lane >> 2;      // 0..7
    const int qc = lane & 3;       // 0..3

    load_stage(0, 0);

    for (int ch = 0; ch < NCH; ch++) {
        if (ch + 1 < NCH) { load_stage((ch + 1) & 1, (ch + 1) * KCH); cp_wait<1>(); }
        else              { cp_wait<0>(); }
        __syncthreads();

        const uint32_t sA = sbase + (ch & 1) * STG;
        const uint32_t sB = sA + TILE_A;

        #pragma unroll
        for (int ks8 = 0; ks8 < 4; ks8++) {
            const int kb = ks8 * 8;
            uint32_t a[4][4];
            #pragma unroll
            for (int mi = 0; mi < 4; mi++) {
                int row = wm * 64 + mi * 16 + qr;
                uint32_t off = sA + row * AROWB + (kb + qc) * 4;
                lds32(a[mi][0], off);
                lds32(a[mi][2], off + 16);
                lds32(a[mi][1], off + 8 * AROWB);
                lds32(a[mi][3], off + 8 * AROWB + 16);
            }
            #pragma unroll
            for (int ni = 0; ni < 8; ni++) {
                int nrow = wn * 64 + ni * 8 + qr;
                uint32_t boff = sB + nrow * AROWB + (kb + qc) * 4;
                uint32_t b0, b1;
                lds32(b0, boff);
                lds32(b1, boff + 16);
                #pragma unroll
                for (int mi = 0; mi < 4; mi++)
                    mma_tf32(acc[mi][ni], a[mi], b0, b1);
            }
        }
        __syncthreads();
    }

    // epilogue: z==0 -> tf32 fp32 Q (scaled 1/8); z==1 -> tf32 fp32 K;
    //           z==2 -> bf16 V (single);    z==3 -> fp32 skip
    if (z < 2) {
        float* Ot = z ? g_kt : g_qt;
        const float sc = (z == 0) ? 0.125f : 1.0f;
        #pragma unroll
        for (int mi = 0; mi < 4; mi++) {
            int row = bm + wm * 64 + mi * 16 + (lane >> 2);
            #pragma unroll
            for (int ni = 0; ni < 8; ni++) {
                int col = bn + wn * 64 + ni * 8 + (lane & 3) * 2;
                float2 b2 = *(const float2*)(bias + col);
                uint2 o0, o1;
                o0.x = to_tf32((acc[mi][ni][0] + b2.x) * sc);
                o0.y = to_tf32((acc[mi][ni][1] + b2.y) * sc);
                o1.x = to_tf32((acc[mi][ni][2] + b2.x) * sc);
                o1.y = to_tf32((acc[mi][ni][3] + b2.y) * sc);
                *(uint2*)(Ot + (size_t)row * CC + col)       = o0;
                *(uint2*)(Ot + (size_t)(row + 8) * CC + col) = o1;
            }
        }
    } else if (z == 2) {
        #pragma unroll
        for (int mi = 0; mi < 4; mi++) {
            int row = bm + wm * 64 + mi * 16 + (lane >> 2);
            #pragma unroll
            for (int ni = 0; ni < 8; ni++) {
                int col = bn + wn * 64 + ni * 8 + (lane & 3) * 2;
                float2 b2 = *(const float2*)(bias + col);
                uint32_t h0 = pack2(acc[mi][ni][0] + b2.x, acc[mi][ni][1] + b2.y);
                uint32_t h1 = pack2(acc[mi][ni][2] + b2.x, acc[mi][ni][3] + b2.y);
                *(uint32_t*)(g_v + (size_t)row * CC + col)       = h0;
                *(uint32_t*)(g_v + (size_t)(row + 8) * CC + col) = h1;
            }
        }
    } else {
        #pragma unroll
        for (int mi = 0; mi < 4; mi++) {
            int row = bm + wm * 64 + mi * 16 + (lane >> 2);
            #pragma unroll
            for (int ni = 0; ni < 8; ni++) {
                int col = bn + wn * 64 + ni * 8 + (lane & 3) * 2;
                float2 b2 = *(const float2*)(bias + col);
                float2 o0 = { acc[mi][ni][0] + b2.x, acc[mi][ni][1] + b2.y };
                float2 o1 = { acc[mi][ni][2] + b2.x, acc[mi][ni][3] + b2.y };
                *(float2*)(g_skip + (size_t)row * CC + col)       = o0;
                *(float2*)(g_skip + (size_t)(row + 8) * CC + col) = o1;
            }
        }
    }
}

// ---- Kernel 2: flash attention, 64-row CTA x 4 warps ----------------------
// S = tf32 single-pass (Q,K fp32-tf32); P·V = single-pass bf16.
#define KTSTR 272                // K fp32 smem row stride bytes (68 floats)
#define KTT   (64 * KTSTR)       // 17408
#define KVSTR 144                // V smem row stride bytes (72 bf16)
#define KVT   (64 * KVSTR)       // 9216
#define XSTR2 272                // Xa smem row stride bytes (68 floats)
#define XAT2  (64 * XSTR2)       // 17408
#define ASTG2 (KTT + KVT + XAT2) // 44032
#define NJT   (NN / 64)          // 64 j-tiles

__global__ __launch_bounds__(128, 2) void attn_mma(
    const float* __restrict__ x, const float* __restrict__ we)
{
    extern __shared__ char dsm[];
    const int tid = threadIdx.x;
    const int wid = tid >> 5;          // 0..3
    const int lane = tid & 31;
    const int h  = blockIdx.y;
    const int i0 = blockIdx.x * 64;
    const int qr = lane >> 2;          // 0..7
    const int qc = lane & 3;           // 0..3

    const uint32_t sbase = smem_u32(dsm);

    // ---- Q fragments (tf32 fp32, pre-scaled 1/8) + qe = (q/8)·we ----
    uint32_t qa[8][4];
    float qe0 = 0.f, qe1 = 0.f;
    {
        const int r0 = i0 + wid * 16 + qr;
        #pragma unroll
        for (int ks = 0; ks < 8; ks++) {
            int col = h * DD + ks * 8 + qc;
            qa[ks][0] = *(const uint32_t*)(g_qt + (size_t)r0 * CC + col);
            qa[ks][1] = *(const uint32_t*)(g_qt + (size_t)(r0 + 8) * CC + col);
            qa[ks][2] = *(const uint32_t*)(g_qt + (size_t)r0 * CC + col + 4);
            qa[ks][3] = *(const uint32_t*)(g_qt + (size_t)(r0 + 8) * CC + col + 4);
            float w0 = __ldg(we + col);
            float w4 = __ldg(we + col + 4);
            qe0 = fmaf(__uint_as_float(qa[ks][0]), w0,
                  fmaf(__uint_as_float(qa[ks][2]), w4, qe0));
            qe1 = fmaf(__uint_as_float(qa[ks][1]), w0,
                  fmaf(__uint_as_float(qa[ks][3]), w4, qe1));
        }
        qe0 += __shfl_xor_sync(0xffffffffu, qe0, 1);
        qe0 += __shfl_xor_sync(0xffffffffu, qe0, 2);
        qe1 += __shfl_xor_sync(0xffffffffu, qe1, 1);
        qe1 += __shfl_xor_sync(0xffffffffu, qe1, 2);
    }

    // stage layout: [Kt fp32 | V bf16 | Xa fp32]
    auto load_stage = [&](int st, int j0) {
        const uint32_t sb = sbase + st * ASTG2;
        #pragma unroll
        for (int n = 0; n < 8; n++) {           // Kt: 1024 chunks
            int id = tid + n * 128;
            int row = id >> 4, c16 = id & 15;
            cp_async16(sb + row * KTSTR + c16 * 16,
                       g_kt + (size_t)(j0 + row) * CC + h * DD + c16 * 4);
        }
        #pragma unroll
        for (int n = 0; n < 4; n++) {           // V: 512 chunks
            int id = tid + n * 128;
            int row = id >> 3, c16 = id & 7;
            cp_async16(sb + KTT + row * KVSTR + c16 * 16,
                       g_v + (size_t)(j0 + row) * CC + h * DD + c16 * 8);
        }
        #pragma unroll
        for (int n = 0; n < 8; n++) {           // Xa: 1024 chunks
            int id = tid + n * 128;
            int row = id >> 4, c16 = id & 15;
            cp_async16(sb + KTT + KVT + row * XSTR2 + c16 * 16,
                       x + (size_t)(j0 + row) * NN + i0 + c16 * 4);
        }
        cp_commit();
    };

    float o[8][4];
    #pragma unroll
    for (int nd = 0; nd < 8; nd++)
        #pragma unroll
        for (int r = 0; r < 4; r++) o[nd][r] = 0.f;
    float m0 = -1e30f, m1 = -1e30f, l0 = 0.f, l1 = 0.f, sa0 = 0.f, sa1 = 0.f;

    const int vrow  = (lane & 7) + ((lane >> 3) & 1) * 8;
    const int vcol8 = ((lane >> 4) & 1) * 8;
    const int iloc0 = wid * 16 + qr;             // 0..63

    load_stage(0, 0);

    for (int jt = 0; jt < NJT; jt++) {
        if (jt + 1 < NJT) { load_stage((jt + 1) & 1, (jt + 1) * 64); cp_wait<1>(); }
        else              { cp_wait<0>(); }
        __syncthreads();

        const uint32_t sb = sbase + (jt & 1) * ASTG2;
        const float* xa = (const float*)(dsm + (size_t)(jt & 1) * ASTG2 + KTT + KVT);

        // ---- S = (Q/8)·K^T via single-pass tf32 MMA ----
        float s[8][4];
        #pragma unroll
        for (int nb = 0; nb < 8; nb++)
            #pragma unroll
            for (int r = 0; r < 4; r++) s[nb][r] = 0.f;

        #pragma unroll
        for (int ks = 0; ks < 8; ks++) {
            #pragma unroll
            for (int nb = 0; nb < 8; nb++) {
                uint32_t boff = sb + (nb * 8 + qr) * KTSTR + (ks * 8 + qc) * 4;
                uint32_t b0, b1;
                lds32(b0, boff);
                lds32(b1, boff + 16);
                mma_tf32(s[nb], qa[ks], b0, b1);
            }
        }

        // ---- edge term + tile max ----
        float tm0 = -1e30f, tm1 = -1e30f;
        #pragma unroll
        for (int nb = 0; nb < 8; nb++) {
            int j = nb * 8 + 2 * qc;
            float x00 = xa[j * 68 + iloc0];
            float x01 = xa[(j + 1) * 68 + iloc0];
            float x10 = xa[j * 68 + iloc0 + 8];
            float x11 = xa[(j + 1) * 68 + iloc0 + 8];
            s[nb][0] = fmaf(x00, qe0, s[nb][0]);
            s[nb][1] = fmaf(x01, qe0, s[nb][1]);
            s[nb][2] = fmaf(x10, qe1, s[nb][2]);
            s[nb][3] = fmaf(x11, qe1, s[nb][3]);
            tm0 = fmaxf(tm0, fmaxf(s[nb][0], s[nb][1]));
            tm1 = fmaxf(tm1, fmaxf(s[nb][2], s[nb][3]));
        }
        tm0 = fmaxf(tm0, __shfl_xor_sync(0xffffffffu, tm0, 1));
        tm0 = fmaxf(tm0, __shfl_xor_sync(0xffffffffu, tm0, 2));
        tm1 = fmaxf(tm1, __shfl_xor_sync(0xffffffffu, tm1, 1));
        tm1 = fmaxf(tm1, __shfl_xor_sync(0xffffffffu, tm1, 2));

        float m0n = fmaxf(m0, tm0), m1n = fmaxf(m1, tm1);
        float sc0 = __expf(m0 - m0n), sc1 = __expf(m1 - m1n);
        l0 *= sc0; sa0 *= sc0; l1 *= sc1; sa1 *= sc1;
        #pragma unroll
        for (int nd = 0; nd < 8; nd++) {
            o[nd][0] *= sc0; o[nd][1] *= sc0;
            o[nd][2] *= sc1; o[nd][3] *= sc1;
        }
        m0 = m0n; m1 = m1n;

        // ---- p = exp(s-m); accumulate l, sacc; overwrite s with p ----
        #pragma unroll
        for (int nb = 0; nb < 8; nb++) {
            int j = nb * 8 + 2 * qc;
            float p0 = __expf(s[nb][0] - m0);
            float p1 = __expf(s[nb][1] - m0);
            float p2 = __expf(s[nb][2] - m1);
            float p3 = __expf(s[nb][3] - m1);
            l0 += p0 + p1; l1 += p2 + p3;
            float x00 = xa[j * 68 + iloc0];
            float x01 = xa[(j + 1) * 68 + iloc0];
            float x10 = xa[j * 68 + iloc0 + 8];
            float x11 = xa[(j + 1) * 68 + iloc0 + 8];
            sa0 = fmaf(p0, x00, fmaf(p1, x01, sa0));
            sa1 = fmaf(p2, x10, fmaf(p3, x11, sa1));
            s[nb][0] = p0; s[nb][1] = p1; s[nb][2] = p2; s[nb][3] = p3;
        }

        // ---- O += P·V (single-pass bf16) ----
        #pragma unroll
        for (int ks = 0; ks < 4; ks++) {
            uint32_t ph[4];
            ph[0] = pack2(s[2 * ks][0],     s[2 * ks][1]);
            ph[1] = pack2(s[2 * ks][2],     s[2 * ks][3]);
            ph[2] = pack2(s[2 * ks + 1][0], s[2 * ks + 1][1]);
            ph[3] = pack2(s[2 * ks + 1][2], s[2 * ks + 1][3]);
            #pragma unroll
            for (int ndp = 0; ndp < 4; ndp++) {
                uint32_t vh4[4];
                uint32_t off = (ks * 16 + vrow) * KVSTR + (ndp * 16 + vcol8) * 2;
                ldm_x4_t(vh4, sb + KTT + off);
                mma_bf16(o[ndp * 2],     ph, vh4[0], vh4[1]);
                mma_bf16(o[ndp * 2 + 1], ph, vh4[2], vh4[3]);
            }
        }
        __syncthreads();
    }

    // ---- epilogue: reduce l/sacc over quad, combine, write g_pre ----
    l0 += __shfl_xor_sync(0xffffffffu, l0, 1);
    l0 += __shfl_xor_sync(0xffffffffu, l0, 2);
    l1 += __shfl_xor_sync(0xffffffffu, l1, 1);
    l1 += __shfl_xor_sync(0xffffffffu, l1, 2);
    sa0 += __shfl_xor_sync(0xffffffffu, sa0, 1);
    sa0 += __shfl_xor_sync(0xffffffffu, sa0, 2);
    sa1 += __shfl_xor_sync(0xffffffffu, sa1, 1);
    sa1 += __shfl_xor_sync(0xffffffffu, sa1, 2);

    float inv0 = 1.f / l0, inv1 = 1.f / l1;
    float se0 = sa0 * inv0, se1 = sa1 * inv1;
    const int gr0 = i0 + wid * 16 + qr;
    #pragma unroll
    for (int nd = 0; nd < 8; nd++) {
        int c = h * DD + nd * 8 + 2 * qc;
        float2 wv  = *(const float2*)(we + c);
        float2 sk0 = *(const float2*)(g_skip + (size_t)gr0 * CC + c);
        float2 sk1 = *(const float2*)(g_skip + (size_t)(gr0 + 8) * CC + c);
        float2 r0, r1;
        r0.x = fmaf(o[nd][0], inv0, fmaf(se0, wv.x, sk0.x));
        r0.y = fmaf(o[nd][1], inv0, fmaf(se0, wv.y, sk0.y));
        r1.x = fmaf(o[nd][2], inv1, fmaf(se1, wv.x, sk1.x));
        r1.y = fmaf(o[nd][3], inv1, fmaf(se1, wv.y, sk1.y));
        *(float2*)(g_pre + (size_t)gr0 * CC + c)       = r0;
        *(float2*)(g_pre + (size_t)(gr0 + 8) * CC + c) = r1;
    }
}

// ---------------- Kernel 3/4: GraphNorm column stats ----------------
__global__ __launch_bounds__(128) void stats_partial()
{
    int c  = blockIdx.x * 128 + threadIdx.x;
    int r0 = blockIdx.y * 128;
    double s = 0.0, s2 = 0.0;
    for (int r = r0; r < r0 + 128; r++) {
        float v = g_pre[(size_t)r * CC + c];
        s  += (double)v;
        s2 += (double)v * (double)v;
    }
    g_psum[blockIdx.y][c] = s;
    g_psq [blockIdx.y][c] = s2;
}

__global__ __launch_bounds__(128) void stats_final(const float* __restrict__ gn_ms)
{
    int c = blockIdx.x * 128 + threadIdx.x;
    double s = 0.0, s2 = 0.0;
    #pragma unroll
    for (int p = 0; p < 32; p++) { s += g_psum[p][c]; s2 += g_psq[p][c]; }
    float mean = (float)(s * (1.0 / NN));
    float ex2  = (float)(s2 * (1.0 / NN));
    float ms   = gn_ms[c];
    float var  = ex2 - 2.f * ms * mean * mean + ms * ms * mean * mean;
    g_mean[c] = mean;
    g_rstd[c] = rsqrtf(var + EPS_GN);
}

// ---------------- Kernel 5: GraphNorm apply + per-row L2 ----------------
__global__ __launch_bounds__(128) void finalize_kernel(
    const float* __restrict__ gn_w, const float* __restrict__ gn_b,
    const float* __restrict__ gn_ms, float* __restrict__ out)
{
    int r = blockIdx.x;
    int tid = threadIdx.x;
    __shared__ float red[4];

    float vals[4];
    float ss = 0.f;
    #pragma unroll
    for (int it = 0; it < 4; it++) {
        int c = tid + it * 128;
        float v = g_pre[(size_t)r * CC + c];
        v = fmaf(gn_w[c] * g_rstd[c], v - gn_ms[c] * g_mean[c], gn_b[c]);
        vals[it] = v;
        ss += v * v;
    }
    #pragma unroll
    for (int off = 16; off; off >>= 1)
        ss += __shfl_xor_sync(0xffffffffu, ss, off);
    if ((tid & 31) == 0) red[tid >> 5] = ss;
    __syncthreads();
    float tot = red[0] + red[1] + red[2] + red[3];
    float inv = rsqrtf(tot);
    #pragma unroll
    for (int it = 0; it < 4; it++)
        out[(size_t)r * CC + tid + it * 128] = vals[it] * inv;
}

// ---------------- launch ----------------
extern "C" void kernel_launch(void* const* d_in, const int* in_sizes, int n_in,
                              void* d_out, int out_size)
{
    const float* x     = (const float*)d_in[0];
    const float* Wq    = (const float*)d_in[1];
    const float* bq    = (const float*)d_in[2];
    const float* Wk    = (const float*)d_in[3];
    const float* bk    = (const float*)d_in[4];
    const float* Wv    = (const float*)d_in[5];
    const float* bv    = (const float*)d_in[6];
    const float* we    = (const float*)d_in[7];
    const float* Wskip = (const float*)d_in[8];
    const float* bskip = (const float*)d_in[9];
    const float* gn_w  = (const float*)d_in[10];
    const float* gn_b  = (const float*)d_in[11];
    const float* gn_ms = (const float*)d_in[12];
    float* out = (float*)d_out;

    const int GEMM_SMEM = 2 * STG;       // 73728 -> 2 CTAs/SM
    cudaFuncSetAttribute(gemm_mma, cudaFuncAttributeMaxDynamicSharedMemorySize,
                         GEMM_SMEM);
    const int ATTN_SMEM = 2 * ASTG2;     // 88064 -> 2 CTAs/SM
    cudaFuncSetAttribute(attn_mma, cudaFuncAttributeMaxDynamicSharedMemorySize,
                         ATTN_SMEM);

    convert_w<<<dim3(NN / 32, CC / 32, 2), dim3(32, 8)>>>(Wq, Wk, 0);
    convert_w<<<dim3(NN / 32, CC / 32, 2), dim3(32, 8)>>>(Wv, Wskip, 2);

    gemm_mma<<<dim3(NN / 128, CC / 128, 4), 128, GEMM_SMEM>>>(x, bq, bk, bv, bskip);

    attn_mma<<<dim3(NN / 64, HH), 128, ATTN_SMEM>>>(x, we);   // launch #4 -> profiled

    stats_partial<<<dim3(4, 32), 128>>>();
    stats_final<<<4, 128>>>(gn_ms);
    finalize_kernel<<<NN, 128>>>(gn_w, gn_b, gn_ms, out);
}